// round 7
// baseline (speedup 1.0000x reference)
#include <cuda_runtime.h>
#include <cstdint>
#include <math.h>

// ---------------------------------------------------------------- constants
#define BATCH 8
#define SEQ   2048
#define CDIM  1024

#define BM 256
#define BN 128
#define BKK 32                      // fp32 elems per stage row = 128 bytes
#define NSTAGES 2
#define A_BYTES (BM*128)            // 32KB
#define B_BYTES (BN*128)            // 16KB
#define STAGE_BYTES (A_BYTES + B_BYTES)
#define SMEM_DYN (NSTAGES*STAGE_BYTES + 1024)

#define SWZ(x) ((x) ^ (((x)>>3)&0x70))

// ---------------------------------------------------------------- scratch
__device__ float g_kqv[(size_t)BATCH*SEQ*3*CDIM];  // [B*T, 3C]
__device__ float g_S  [(size_t)BATCH*SEQ*SEQ];     // [B, T, T]
__device__ float g_O  [(size_t)BATCH*SEQ*CDIM];    // [B*T, C]
__device__ float g_Wt [(size_t)3*CDIM*CDIM];       // W_kqv^T  [3C, C]
__device__ float g_WtP[(size_t)CDIM*CDIM];         // W_proj^T [C, C]
__device__ float g_Vt [(size_t)BATCH*CDIM*SEQ];    // V^T per batch [C, T]

// ---------------------------------------------------------------- ptx utils
__device__ __forceinline__ uint32_t smem_u32(const void* p){
    uint32_t a;
    asm("{ .reg .u64 t; cvta.to.shared.u64 t, %1; cvt.u32.u64 %0, t; }"
        : "=r"(a) : "l"(p));
    return a;
}
__device__ __forceinline__ void cp16(uint32_t dst, const void* src){
    asm volatile("cp.async.ca.shared.global [%0], [%1], 16;" :: "r"(dst), "l"(src));
}
#define CP_COMMIT() asm volatile("cp.async.commit_group;" ::: "memory")
#define CP_WAIT1()  asm volatile("cp.async.wait_group 1;" ::: "memory")

__device__ __forceinline__ void ldm_x4(uint32_t& r0, uint32_t& r1,
                                       uint32_t& r2, uint32_t& r3, uint32_t a){
    asm volatile("ldmatrix.sync.aligned.m8n8.x4.shared.b16 {%0,%1,%2,%3}, [%4];"
        : "=r"(r0), "=r"(r1), "=r"(r2), "=r"(r3) : "r"(a));
}
#define CVT_TF32(x) asm volatile("cvt.rna.tf32.f32 %0, %0;" : "+r"(x))

__device__ __forceinline__ float tf32r(float x){
    uint32_t u = __float_as_uint(x);
    asm("cvt.rna.tf32.f32 %0, %0;" : "+r"(u));
    return __uint_as_float(u);
}

__device__ __forceinline__ void mma_m16n8k8(float* c, const uint32_t* a,
                                            uint32_t b0, uint32_t b1){
    asm volatile(
        "mma.sync.aligned.m16n8k8.row.col.f32.tf32.tf32.f32 "
        "{%0,%1,%2,%3}, {%4,%5,%6,%7}, {%8,%9}, {%0,%1,%2,%3};"
        : "+f"(c[0]), "+f"(c[1]), "+f"(c[2]), "+f"(c[3])
        : "r"(a[0]), "r"(a[1]), "r"(a[2]), "r"(a[3]), "r"(b0), "r"(b1));
}

// ---------------------------------------------------------------- tile loader
// A-tile: 256 rows x 32 fp32 (8 cp16/thread); B-tile: 128 rows (4 cp16/thread)
__device__ __forceinline__ void load_tile(uint32_t sA, uint32_t sB,
    const float* __restrict__ Ab, const float* __restrict__ Bb,
    int lda, int ldb, int k0, int tid)
{
#pragma unroll
    for (int i = 0; i < 8; i++) {
        int idx = tid + i*256;
        int row = idx >> 3;
        int ck  = (idx & 7) << 2;
        uint32_t so = SWZ((uint32_t)(row*128 + ck*4));
        cp16(sA + so, Ab + (size_t)row*lda + k0 + ck);
    }
#pragma unroll
    for (int i = 0; i < 4; i++) {
        int idx = tid + i*256;
        int row = idx >> 3;
        int ck  = (idx & 7) << 2;
        uint32_t so = SWZ((uint32_t)(row*128 + ck*4));
        cp16(sB + so, Bb + (size_t)row*ldb + k0 + ck);
    }
}

// ---------------------------------------------------------------- mma GEMM
// C[bz][m][n] = alpha * sum_k A[bz][m][k] * B[bz][n][k]  (+ bias[n])
// NT gemm, tf32 tensor cores. 256x128 CTA tile, 8 warps (4x2) of 64x64.
// CSKIP: causal skip for BM=2*BN (skip if bx > 2*by+1).
template<bool CSKIP, bool CK, bool HB, bool CVTA, bool ROUND>
__global__ void __launch_bounds__(256) gemm_tc(
    const float* __restrict__ A, const float* __restrict__ B,
    float* __restrict__ C, const float* __restrict__ bias,
    int K, int lda, int ldb, int ldc, long sA, long sB, long sC, float alpha)
{
    const int bx = blockIdx.x, by = blockIdx.y, bz = blockIdx.z;
    if (CSKIP && bx > 2*by + 1) return;

    extern __shared__ char smem[];
    const uint32_t tb = (smem_u32(smem) + 1023) & ~1023u;
    const int tid = threadIdx.x, wid = tid >> 5, lid = tid & 31;
    const int wm = wid >> 1;       // 4 m-blocks of 64
    const int wn = wid & 1;        // 2 n-blocks of 64

    const float* Ab = A + (size_t)bz*sA + (size_t)by*BM*lda;
    const float* Bb = B + (size_t)bz*sB + (size_t)bx*BN*ldb;
    float* Cb = C + (size_t)bz*sC;
    const int kEnd = CK ? min(K, (by + 1)*BM) : K;
    const int iters = kEnd >> 5;

    float acc[4][8][4];
#pragma unroll
    for (int i = 0; i < 4; i++)
#pragma unroll
        for (int j = 0; j < 8; j++)
#pragma unroll
            for (int r = 0; r < 4; r++) acc[i][j][r] = 0.0f;

    const uint32_t aRow  = (uint32_t)((wm*64 + (lid & 15)) * 128);
    const uint32_t aKoff = (uint32_t)((lid >> 4) * 16);
    const uint32_t bRow  = (uint32_t)((wn*64 + (lid & 7) + ((lid >> 4) * 8)) * 128);
    const uint32_t bKoff = (uint32_t)(((lid >> 3) & 1) * 16);

#pragma unroll
    for (int s = 0; s < NSTAGES; s++) {
        load_tile(tb + s*STAGE_BYTES, tb + s*STAGE_BYTES + A_BYTES,
                  Ab, Bb, lda, ldb, s*BKK, tid);
        CP_COMMIT();
    }

    for (int it = 0; it < iters; ++it) {
        const int s = it & 1;
        const uint32_t sAb = tb + s*STAGE_BYTES;
        const uint32_t sBb = sAb + A_BYTES;
        CP_WAIT1();
        __syncthreads();

#pragma unroll
        for (int kc = 0; kc < 4; kc++) {
            const uint32_t kb = (uint32_t)(kc * 32);
            uint32_t a[4][4];
#pragma unroll
            for (int i = 0; i < 4; i++) {
                uint32_t off = aRow + (uint32_t)(i*16*128) + kb + aKoff;
                ldm_x4(a[i][0], a[i][1], a[i][2], a[i][3], sAb + SWZ(off));
            }
            uint32_t b[4][4];
#pragma unroll
            for (int p = 0; p < 4; p++) {
                uint32_t off = bRow + (uint32_t)(p*16*128) + kb + bKoff;
                ldm_x4(b[p][0], b[p][1], b[p][2], b[p][3], sBb + SWZ(off));
            }
            if (CVTA) {
#pragma unroll
                for (int i = 0; i < 4; i++) {
                    CVT_TF32(a[i][0]); CVT_TF32(a[i][1]);
                    CVT_TF32(a[i][2]); CVT_TF32(a[i][3]);
                }
            }
#pragma unroll
            for (int i = 0; i < 4; i++)
#pragma unroll
                for (int j = 0; j < 8; j++)
                    mma_m16n8k8(acc[i][j], a[i],
                                b[j >> 1][(j & 1)*2], b[j >> 1][(j & 1)*2 + 1]);
        }

        __syncthreads();
        const int nit = it + NSTAGES;
        if (nit < iters)
            load_tile(tb + s*STAGE_BYTES, tb + s*STAGE_BYTES + A_BYTES,
                      Ab, Bb, lda, ldb, nit*BKK, tid);
        CP_COMMIT();
    }

    const int rowg = by*BM + wm*64 + (lid >> 2);
    const int colg = bx*BN + wn*64 + (lid & 3)*2;
#pragma unroll
    for (int j = 0; j < 8; j++) {
        const int c = colg + j*8;
        float2 bv = make_float2(0.f, 0.f);
        if (HB) bv = *(const float2*)(bias + c);
#pragma unroll
        for (int i = 0; i < 4; i++) {
            const int r = rowg + i*16;
            float2 v0, v1;
            v0.x = acc[i][j][0]*alpha + bv.x;
            v0.y = acc[i][j][1]*alpha + bv.y;
            v1.x = acc[i][j][2]*alpha + bv.x;
            v1.y = acc[i][j][3]*alpha + bv.y;
            if (ROUND) {
                v0.x = tf32r(v0.x); v0.y = tf32r(v0.y);
                v1.x = tf32r(v1.x); v1.y = tf32r(v1.y);
            }
            *(float2*)(Cb + (size_t)r*ldc + c)     = v0;
            *(float2*)(Cb + (size_t)(r+8)*ldc + c) = v1;
        }
    }
}

// ---------------------------------------------------------------- transpose
__global__ void __launch_bounds__(256) transpose_g(
    const float* __restrict__ in, float* __restrict__ out,
    int ldin, int ldout, long sIn, long sOut)
{
    __shared__ float t[32][33];
    const int b = blockIdx.z;
    in  += (size_t)b * sIn;
    out += (size_t)b * sOut;
    const int x = blockIdx.x * 32;
    const int y = blockIdx.y * 32;
#pragma unroll
    for (int j = threadIdx.y; j < 32; j += 8)
        t[j][threadIdx.x] = tf32r(in[(size_t)(y + j)*ldin + x + threadIdx.x]);
    __syncthreads();
#pragma unroll
    for (int j = threadIdx.y; j < 32; j += 8)
        out[(size_t)(x + j)*ldout + y + threadIdx.x] = t[threadIdx.x][j];
}

// ---------------------------------------------------------------- softmax
__global__ __launch_bounds__(256)
void softmax_causal(float* __restrict__ S, int T)
{
    const int i = blockIdx.x;
    const int b = blockIdx.y;
    float* row = S + ((size_t)b*T + i)*T;
    const int L = i + 1;
    const int tid = threadIdx.x;

    __shared__ float red[8];
    __shared__ float bval;

    float m = -1e30f;
    for (int j = tid; j < L; j += 256) m = fmaxf(m, row[j]);
#pragma unroll
    for (int o = 16; o; o >>= 1) m = fmaxf(m, __shfl_xor_sync(0xffffffffu, m, o));
    if ((tid & 31) == 0) red[tid >> 5] = m;
    __syncthreads();
    if (tid == 0) {
        float mm = red[0];
#pragma unroll
        for (int w = 1; w < 8; w++) mm = fmaxf(mm, red[w]);
        bval = mm;
    }
    __syncthreads();
    m = bval;
    __syncthreads();

    float s = 0.0f;
    for (int j = tid; j < L; j += 256) {
        float e = expf(row[j] - m);
        row[j] = e;
        s += e;
    }
#pragma unroll
    for (int o = 16; o; o >>= 1) s += __shfl_xor_sync(0xffffffffu, s, o);
    if ((tid & 31) == 0) red[tid >> 5] = s;
    __syncthreads();
    if (tid == 0) {
        float ss = 0.0f;
#pragma unroll
        for (int w = 0; w < 8; w++) ss += red[w];
        bval = ss;
    }
    __syncthreads();
    const float inv = 1.0f / bval;

    for (int j = tid; j < L; j += 256) row[j] = tf32r(row[j] * inv);
    // zero to 256-row block end: PV GEMM k-limit is 256-granular now
    const int end = ((i >> 8) + 1) << 8;
    for (int j = L + tid; j < end; j += 256) row[j] = 0.0f;
}

// ---------------------------------------------------------------- launch
extern "C" void kernel_launch(void* const* d_in, const int* in_sizes, int n_in,
                              void* d_out, int out_size)
{
    (void)in_sizes; (void)n_in; (void)out_size;
    const float* x      = (const float*)d_in[0];
    const float* W_kqv  = (const float*)d_in[1];
    const float* b_kqv  = (const float*)d_in[2];
    const float* W_proj = (const float*)d_in[3];
    const float* b_proj = (const float*)d_in[4];
    float* out = (float*)d_out;

    float *kqv, *S, *O, *Wt, *WtP, *Vt;
    cudaGetSymbolAddress((void**)&kqv, g_kqv);
    cudaGetSymbolAddress((void**)&S,   g_S);
    cudaGetSymbolAddress((void**)&O,   g_O);
    cudaGetSymbolAddress((void**)&Wt,  g_Wt);
    cudaGetSymbolAddress((void**)&WtP, g_WtP);
    cudaGetSymbolAddress((void**)&Vt,  g_Vt);

    const int B = BATCH, T = SEQ, C = CDIM;
    const float scale = 1.0f / sqrtf((float)T);
    const long sBT3C = (long)T*3*C;

    cudaFuncSetAttribute(gemm_tc<false,false,true,true,true>,
        cudaFuncAttributeMaxDynamicSharedMemorySize, SMEM_DYN);
    cudaFuncSetAttribute(gemm_tc<true,false,false,false,false>,
        cudaFuncAttributeMaxDynamicSharedMemorySize, SMEM_DYN);
    cudaFuncSetAttribute(gemm_tc<false,true,false,false,true>,
        cudaFuncAttributeMaxDynamicSharedMemorySize, SMEM_DYN);
    cudaFuncSetAttribute(gemm_tc<false,false,true,false,false>,
        cudaFuncAttributeMaxDynamicSharedMemorySize, SMEM_DYN);

    // 1) Wt = W_kqv^T (tf32-rounded)
    transpose_g<<<dim3(3*C/32, C/32, 1), dim3(32,8)>>>(W_kqv, Wt, 3*C, C, 0, 0);

    // 2) kqv = x @ W_kqv + b_kqv
    gemm_tc<false,false,true,true,true><<<dim3(3*C/BN, (B*T)/BM, 1), 256, SMEM_DYN>>>(
        x, Wt, kqv, b_kqv, C, C, C, 3*C, 0, 0, 0, 1.0f);

    // 3) Vt[b][c][t] = kqv[b*T+t][2C+c]
    transpose_g<<<dim3(C/32, T/32, B), dim3(32,8)>>>(
        kqv + 2*C, Vt, 3*C, T, sBT3C, (long)C*T);

    // 4) S = Q @ K^T * scale (causal block-skip, 256x128 blocks)
    gemm_tc<true,false,false,false,false><<<dim3(T/BN, T/BM, B), 256, SMEM_DYN>>>(
        kqv + C, kqv, S, nullptr, C, 3*C, 3*C, T,
        sBT3C, sBT3C, (long)T*T, scale);

    // 5) causal softmax (tf32-rounded P, zeros to 256-block ends)
    softmax_causal<<<dim3(T, B, 1), 256>>>(S, T);

    // 6) O = P @ V (causal k-limit, 256-granular)  <-- ncu-profiled launch
    gemm_tc<false,true,false,false,true><<<dim3(C/BN, T/BM, B), 256, SMEM_DYN>>>(
        S, Vt, O, nullptr, T, T, T, C,
        (long)T*T, (long)C*T, (long)T*C, 1.0f);

    // 7) WtP = W_proj^T
    transpose_g<<<dim3(C/32, C/32, 1), dim3(32,8)>>>(W_proj, WtP, C, C, 0, 0);

    // 8) out = O @ W_proj + b_proj
    gemm_tc<false,false,true,false,false><<<dim3(C/BN, (B*T)/BM, 1), 256, SMEM_DYN>>>(
        O, WtP, out, b_proj, C, C, C, C, 0, 0, 0, 1.0f);
}

// round 8
// speedup vs baseline: 1.0401x; 1.0401x over previous
#include <cuda_runtime.h>
#include <cstdint>
#include <math.h>

// ---------------------------------------------------------------- constants
#define BATCH 8
#define SEQ   2048
#define CDIM  1024

#define BM 256
#define BN 128
#define BKK 32                      // fp32 elems per stage row = 128 bytes
#define NSTAGES 2
#define A_BYTES (BM*128)            // 32KB
#define B_BYTES (BN*128)            // 16KB
#define STAGE_BYTES (A_BYTES + B_BYTES)
#define SMEM_DYN (NSTAGES*STAGE_BYTES + 1024)

#define SWZ(x) ((x) ^ (((x)>>3)&0x70))

// ---------------------------------------------------------------- scratch
__device__ float g_kqv[(size_t)BATCH*SEQ*3*CDIM];  // [B*T, 3C]
__device__ float g_S  [(size_t)BATCH*SEQ*SEQ];     // [B, T, T]
__device__ float g_O  [(size_t)BATCH*SEQ*CDIM];    // [B*T, C]
__device__ float g_Wt [(size_t)3*CDIM*CDIM];       // W_kqv^T  [3C, C]
__device__ float g_WtP[(size_t)CDIM*CDIM];         // W_proj^T [C, C]
__device__ float g_Vt [(size_t)BATCH*CDIM*SEQ];    // V^T per batch [C, T]

// ---------------------------------------------------------------- ptx utils
__device__ __forceinline__ uint32_t smem_u32(const void* p){
    uint32_t a;
    asm("{ .reg .u64 t; cvta.to.shared.u64 t, %1; cvt.u32.u64 %0, t; }"
        : "=r"(a) : "l"(p));
    return a;
}
// .cg: bypass L1 (staged data is consumed once from SMEM; keeps L1 for LDSM)
__device__ __forceinline__ void cp16(uint32_t dst, const void* src){
    asm volatile("cp.async.cg.shared.global [%0], [%1], 16;" :: "r"(dst), "l"(src));
}
#define CP_COMMIT() asm volatile("cp.async.commit_group;" ::: "memory")
#define CP_WAIT1()  asm volatile("cp.async.wait_group 1;" ::: "memory")

__device__ __forceinline__ void ldm_x4(uint32_t& r0, uint32_t& r1,
                                       uint32_t& r2, uint32_t& r3, uint32_t a){
    asm volatile("ldmatrix.sync.aligned.m8n8.x4.shared.b16 {%0,%1,%2,%3}, [%4];"
        : "=r"(r0), "=r"(r1), "=r"(r2), "=r"(r3) : "r"(a));
}
#define CVT_TF32(x) asm volatile("cvt.rna.tf32.f32 %0, %0;" : "+r"(x))

__device__ __forceinline__ float tf32r(float x){
    uint32_t u = __float_as_uint(x);
    asm("cvt.rna.tf32.f32 %0, %0;" : "+r"(u));
    return __uint_as_float(u);
}

__device__ __forceinline__ void mma_m16n8k8(float* c, const uint32_t* a,
                                            uint32_t b0, uint32_t b1){
    asm volatile(
        "mma.sync.aligned.m16n8k8.row.col.f32.tf32.tf32.f32 "
        "{%0,%1,%2,%3}, {%4,%5,%6,%7}, {%8,%9}, {%0,%1,%2,%3};"
        : "+f"(c[0]), "+f"(c[1]), "+f"(c[2]), "+f"(c[3])
        : "r"(a[0]), "r"(a[1]), "r"(a[2]), "r"(a[3]), "r"(b0), "r"(b1));
}

// ---------------------------------------------------------------- tile loader
__device__ __forceinline__ void load_tile(uint32_t sA, uint32_t sB,
    const float* __restrict__ Ab, const float* __restrict__ Bb,
    int lda, int ldb, int k0, int tid)
{
#pragma unroll
    for (int i = 0; i < 8; i++) {
        int idx = tid + i*256;
        int row = idx >> 3;
        int ck  = (idx & 7) << 2;
        uint32_t so = SWZ((uint32_t)(row*128 + ck*4));
        cp16(sA + so, Ab + (size_t)row*lda + k0 + ck);
    }
#pragma unroll
    for (int i = 0; i < 4; i++) {
        int idx = tid + i*256;
        int row = idx >> 3;
        int ck  = (idx & 7) << 2;
        uint32_t so = SWZ((uint32_t)(row*128 + ck*4));
        cp16(sB + so, Bb + (size_t)row*ldb + k0 + ck);
    }
}

// ---------------------------------------------------------------- mma GEMM
// C[bz][m][n] = alpha * sum_k A[bz][m][k] * B[bz][n][k]  (+ bias[n])
// NT gemm, tf32 tensor cores. 256x128 CTA tile, 8 warps (4x2) of 64x64.
// Fragment double-buffering across k-chunks hides LDSM latency under MMA issue.
template<bool CSKIP, bool CK, bool HB, bool CVTA, bool ROUND>
__global__ void __launch_bounds__(256) gemm_tc(
    const float* __restrict__ A, const float* __restrict__ B,
    float* __restrict__ C, const float* __restrict__ bias,
    int K, int lda, int ldb, int ldc, long sA, long sB, long sC, float alpha)
{
    const int bx = blockIdx.x, by = blockIdx.y, bz = blockIdx.z;
    if (CSKIP && bx > 2*by + 1) return;

    extern __shared__ char smem[];
    const uint32_t tb = (smem_u32(smem) + 1023) & ~1023u;
    const int tid = threadIdx.x, wid = tid >> 5, lid = tid & 31;
    const int wm = wid >> 1;       // 4 m-blocks of 64
    const int wn = wid & 1;        // 2 n-blocks of 64

    const float* Ab = A + (size_t)bz*sA + (size_t)by*BM*lda;
    const float* Bb = B + (size_t)bz*sB + (size_t)bx*BN*ldb;
    float* Cb = C + (size_t)bz*sC;
    const int kEnd = CK ? min(K, (by + 1)*BM) : K;
    const int iters = kEnd >> 5;

    float acc[4][8][4];
#pragma unroll
    for (int i = 0; i < 4; i++)
#pragma unroll
        for (int j = 0; j < 8; j++)
#pragma unroll
            for (int r = 0; r < 4; r++) acc[i][j][r] = 0.0f;

    const uint32_t aRow  = (uint32_t)((wm*64 + (lid & 15)) * 128);
    const uint32_t aKoff = (uint32_t)((lid >> 4) * 16);
    const uint32_t bRow  = (uint32_t)((wn*64 + (lid & 7) + ((lid >> 4) * 8)) * 128);
    const uint32_t bKoff = (uint32_t)(((lid >> 3) & 1) * 16);

#pragma unroll
    for (int s = 0; s < NSTAGES; s++) {
        load_tile(tb + s*STAGE_BYTES, tb + s*STAGE_BYTES + A_BYTES,
                  Ab, Bb, lda, ldb, s*BKK, tid);
        CP_COMMIT();
    }

    uint32_t afr[2][4][4], bfr[2][4][4];

    for (int it = 0; it < iters; ++it) {
        const int s = it & 1;
        const uint32_t sAb = tb + s*STAGE_BYTES;
        const uint32_t sBb = sAb + A_BYTES;
        CP_WAIT1();
        __syncthreads();

        // preload kc=0 fragments
#pragma unroll
        for (int i = 0; i < 4; i++) {
            uint32_t off = aRow + (uint32_t)(i*16*128) + aKoff;
            ldm_x4(afr[0][i][0], afr[0][i][1], afr[0][i][2], afr[0][i][3],
                   sAb + SWZ(off));
        }
#pragma unroll
        for (int p = 0; p < 4; p++) {
            uint32_t off = bRow + (uint32_t)(p*16*128) + bKoff;
            ldm_x4(bfr[0][p][0], bfr[0][p][1], bfr[0][p][2], bfr[0][p][3],
                   sBb + SWZ(off));
        }

#pragma unroll
        for (int kc = 0; kc < 4; kc++) {
            const int cur = kc & 1, nxt = cur ^ 1;
            if (kc < 3) {
                const uint32_t kb = (uint32_t)((kc + 1) * 32);
#pragma unroll
                for (int i = 0; i < 4; i++) {
                    uint32_t off = aRow + (uint32_t)(i*16*128) + kb + aKoff;
                    ldm_x4(afr[nxt][i][0], afr[nxt][i][1],
                           afr[nxt][i][2], afr[nxt][i][3], sAb + SWZ(off));
                }
#pragma unroll
                for (int p = 0; p < 4; p++) {
                    uint32_t off = bRow + (uint32_t)(p*16*128) + kb + bKoff;
                    ldm_x4(bfr[nxt][p][0], bfr[nxt][p][1],
                           bfr[nxt][p][2], bfr[nxt][p][3], sBb + SWZ(off));
                }
            }
            if (CVTA) {
#pragma unroll
                for (int i = 0; i < 4; i++) {
                    CVT_TF32(afr[cur][i][0]); CVT_TF32(afr[cur][i][1]);
                    CVT_TF32(afr[cur][i][2]); CVT_TF32(afr[cur][i][3]);
                }
            }
#pragma unroll
            for (int i = 0; i < 4; i++)
#pragma unroll
                for (int j = 0; j < 8; j++)
                    mma_m16n8k8(acc[i][j], afr[cur][i],
                                bfr[cur][j >> 1][(j & 1)*2],
                                bfr[cur][j >> 1][(j & 1)*2 + 1]);
        }

        __syncthreads();
        const int nit = it + NSTAGES;
        if (nit < iters)
            load_tile(tb + s*STAGE_BYTES, tb + s*STAGE_BYTES + A_BYTES,
                      Ab, Bb, lda, ldb, nit*BKK, tid);
        CP_COMMIT();
    }

    const int rowg = by*BM + wm*64 + (lid >> 2);
    const int colg = bx*BN + wn*64 + (lid & 3)*2;
#pragma unroll
    for (int j = 0; j < 8; j++) {
        const int c = colg + j*8;
        float2 bv = make_float2(0.f, 0.f);
        if (HB) bv = *(const float2*)(bias + c);
#pragma unroll
        for (int i = 0; i < 4; i++) {
            const int r = rowg + i*16;
            float2 v0, v1;
            v0.x = acc[i][j][0]*alpha + bv.x;
            v0.y = acc[i][j][1]*alpha + bv.y;
            v1.x = acc[i][j][2]*alpha + bv.x;
            v1.y = acc[i][j][3]*alpha + bv.y;
            if (ROUND) {
                v0.x = tf32r(v0.x); v0.y = tf32r(v0.y);
                v1.x = tf32r(v1.x); v1.y = tf32r(v1.y);
            }
            *(float2*)(Cb + (size_t)r*ldc + c)     = v0;
            *(float2*)(Cb + (size_t)(r+8)*ldc + c) = v1;
        }
    }
}

// ---------------------------------------------------------------- transpose
__global__ void __launch_bounds__(256) transpose_g(
    const float* __restrict__ in, float* __restrict__ out,
    int ldin, int ldout, long sIn, long sOut)
{
    __shared__ float t[32][33];
    const int b = blockIdx.z;
    in  += (size_t)b * sIn;
    out += (size_t)b * sOut;
    const int x = blockIdx.x * 32;
    const int y = blockIdx.y * 32;
#pragma unroll
    for (int j = threadIdx.y; j < 32; j += 8)
        t[j][threadIdx.x] = tf32r(in[(size_t)(y + j)*ldin + x + threadIdx.x]);
    __syncthreads();
#pragma unroll
    for (int j = threadIdx.y; j < 32; j += 8)
        out[(size_t)(x + j)*ldout + y + threadIdx.x] = t[threadIdx.x][j];
}

// ---------------------------------------------------------------- softmax
__global__ __launch_bounds__(256)
void softmax_causal(float* __restrict__ S, int T)
{
    const int i = blockIdx.x;
    const int b = blockIdx.y;
    float* row = S + ((size_t)b*T + i)*T;
    const int L = i + 1;
    const int tid = threadIdx.x;

    __shared__ float red[8];
    __shared__ float bval;

    float m = -1e30f;
    for (int j = tid; j < L; j += 256) m = fmaxf(m, row[j]);
#pragma unroll
    for (int o = 16; o; o >>= 1) m = fmaxf(m, __shfl_xor_sync(0xffffffffu, m, o));
    if ((tid & 31) == 0) red[tid >> 5] = m;
    __syncthreads();
    if (tid == 0) {
        float mm = red[0];
#pragma unroll
        for (int w = 1; w < 8; w++) mm = fmaxf(mm, red[w]);
        bval = mm;
    }
    __syncthreads();
    m = bval;
    __syncthreads();

    float s = 0.0f;
    for (int j = tid; j < L; j += 256) {
        float e = expf(row[j] - m);
        row[j] = e;
        s += e;
    }
#pragma unroll
    for (int o = 16; o; o >>= 1) s += __shfl_xor_sync(0xffffffffu, s, o);
    if ((tid & 31) == 0) red[tid >> 5] = s;
    __syncthreads();
    if (tid == 0) {
        float ss = 0.0f;
#pragma unroll
        for (int w = 0; w < 8; w++) ss += red[w];
        bval = ss;
    }
    __syncthreads();
    const float inv = 1.0f / bval;

    for (int j = tid; j < L; j += 256) row[j] = tf32r(row[j] * inv);
    // zero to 256-row block end: PV GEMM k-limit is 256-granular
    const int end = ((i >> 8) + 1) << 8;
    for (int j = L + tid; j < end; j += 256) row[j] = 0.0f;
}

// ---------------------------------------------------------------- launch
extern "C" void kernel_launch(void* const* d_in, const int* in_sizes, int n_in,
                              void* d_out, int out_size)
{
    (void)in_sizes; (void)n_in; (void)out_size;
    const float* x      = (const float*)d_in[0];
    const float* W_kqv  = (const float*)d_in[1];
    const float* b_kqv  = (const float*)d_in[2];
    const float* W_proj = (const float*)d_in[3];
    const float* b_proj = (const float*)d_in[4];
    float* out = (float*)d_out;

    float *kqv, *S, *O, *Wt, *WtP, *Vt;
    cudaGetSymbolAddress((void**)&kqv, g_kqv);
    cudaGetSymbolAddress((void**)&S,   g_S);
    cudaGetSymbolAddress((void**)&O,   g_O);
    cudaGetSymbolAddress((void**)&Wt,  g_Wt);
    cudaGetSymbolAddress((void**)&WtP, g_WtP);
    cudaGetSymbolAddress((void**)&Vt,  g_Vt);

    const int B = BATCH, T = SEQ, C = CDIM;
    const float scale = 1.0f / sqrtf((float)T);
    const long sBT3C = (long)T*3*C;

    cudaFuncSetAttribute(gemm_tc<false,false,true,true,true>,
        cudaFuncAttributeMaxDynamicSharedMemorySize, SMEM_DYN);
    cudaFuncSetAttribute(gemm_tc<true,false,false,false,false>,
        cudaFuncAttributeMaxDynamicSharedMemorySize, SMEM_DYN);
    cudaFuncSetAttribute(gemm_tc<false,true,false,false,true>,
        cudaFuncAttributeMaxDynamicSharedMemorySize, SMEM_DYN);
    cudaFuncSetAttribute(gemm_tc<false,false,true,false,false>,
        cudaFuncAttributeMaxDynamicSharedMemorySize, SMEM_DYN);

    // 1) Wt = W_kqv^T (tf32-rounded)
    transpose_g<<<dim3(3*C/32, C/32, 1), dim3(32,8)>>>(W_kqv, Wt, 3*C, C, 0, 0);

    // 2) kqv = x @ W_kqv + b_kqv
    gemm_tc<false,false,true,true,true><<<dim3(3*C/BN, (B*T)/BM, 1), 256, SMEM_DYN>>>(
        x, Wt, kqv, b_kqv, C, C, C, 3*C, 0, 0, 0, 1.0f);

    // 3) Vt[b][c][t] = kqv[b*T+t][2C+c]
    transpose_g<<<dim3(C/32, T/32, B), dim3(32,8)>>>(
        kqv + 2*C, Vt, 3*C, T, sBT3C, (long)C*T);

    // 4) S = Q @ K^T * scale (causal block-skip, 256x128 blocks)
    gemm_tc<true,false,false,false,false><<<dim3(T/BN, T/BM, B), 256, SMEM_DYN>>>(
        kqv + C, kqv, S, nullptr, C, 3*C, 3*C, T,
        sBT3C, sBT3C, (long)T*T, scale);

    // 5) causal softmax (tf32-rounded P, zeros to 256-block ends)
    softmax_causal<<<dim3(T, B, 1), 256>>>(S, T);

    // 6) O = P @ V (causal k-limit, 256-granular)
    gemm_tc<false,true,false,false,true><<<dim3(C/BN, T/BM, B), 256, SMEM_DYN>>>(
        S, Vt, O, nullptr, T, T, T, C,
        (long)T*T, (long)C*T, (long)T*C, 1.0f);

    // 7) WtP = W_proj^T
    transpose_g<<<dim3(C/32, C/32, 1), dim3(32,8)>>>(W_proj, WtP, C, C, 0, 0);

    // 8) out = O @ W_proj + b_proj
    gemm_tc<false,false,true,false,false><<<dim3(C/BN, (B*T)/BM, 1), 256, SMEM_DYN>>>(
        O, WtP, out, b_proj, C, C, C, C, 0, 0, 0, 1.0f);
}

// round 9
// speedup vs baseline: 1.1124x; 1.0695x over previous
#include <cuda_runtime.h>
#include <cstdint>
#include <math.h>

// ---------------------------------------------------------------- constants
#define BATCH 8
#define SEQ   2048
#define CDIM  1024

#define BM 256
#define BN 128
#define BKK 32                      // fp32 elems per stage row = 128 bytes
#define NSTAGES 3
#define A_BYTES (BM*128)            // 32KB
#define B_BYTES (BN*128)            // 16KB
#define STAGE_BYTES (A_BYTES + B_BYTES)
#define SMEM_DYN (NSTAGES*STAGE_BYTES + 1024)

#define SWZ(x) ((x) ^ (((x)>>3)&0x70))

// ---------------------------------------------------------------- scratch
__device__ float g_kqv[(size_t)BATCH*SEQ*3*CDIM];  // [B*T, 3C]
__device__ float g_S  [(size_t)BATCH*SEQ*SEQ];     // [B, T, T]
__device__ float g_O  [(size_t)BATCH*SEQ*CDIM];    // [B*T, C]
__device__ float g_Wt [(size_t)3*CDIM*CDIM];       // W_kqv^T  [3C, C]
__device__ float g_WtP[(size_t)CDIM*CDIM];         // W_proj^T [C, C]
__device__ float g_Vt [(size_t)BATCH*CDIM*SEQ];    // V^T per batch [C, T]

// ---------------------------------------------------------------- ptx utils
__device__ __forceinline__ uint32_t smem_u32(const void* p){
    uint32_t a;
    asm("{ .reg .u64 t; cvta.to.shared.u64 t, %1; cvt.u32.u64 %0, t; }"
        : "=r"(a) : "l"(p));
    return a;
}
// .cg: bypass L1 (staged data is consumed once from SMEM)
__device__ __forceinline__ void cp16(uint32_t dst, const void* src){
    asm volatile("cp.async.cg.shared.global [%0], [%1], 16;" :: "r"(dst), "l"(src));
}
#define CP_COMMIT() asm volatile("cp.async.commit_group;" ::: "memory")
#define CP_WAIT1()  asm volatile("cp.async.wait_group 1;" ::: "memory")

__device__ __forceinline__ void ldm_x4(uint32_t& r0, uint32_t& r1,
                                       uint32_t& r2, uint32_t& r3, uint32_t a){
    asm volatile("ldmatrix.sync.aligned.m8n8.x4.shared.b16 {%0,%1,%2,%3}, [%4];"
        : "=r"(r0), "=r"(r1), "=r"(r2), "=r"(r3) : "r"(a));
}
#define CVT_TF32(x) asm volatile("cvt.rna.tf32.f32 %0, %0;" : "+r"(x))

__device__ __forceinline__ float tf32r(float x){
    uint32_t u = __float_as_uint(x);
    asm("cvt.rna.tf32.f32 %0, %0;" : "+r"(u));
    return __uint_as_float(u);
}

__device__ __forceinline__ void mma_m16n8k8(float* c, const uint32_t* a,
                                            uint32_t b0, uint32_t b1){
    asm volatile(
        "mma.sync.aligned.m16n8k8.row.col.f32.tf32.tf32.f32 "
        "{%0,%1,%2,%3}, {%4,%5,%6,%7}, {%8,%9}, {%0,%1,%2,%3};"
        : "+f"(c[0]), "+f"(c[1]), "+f"(c[2]), "+f"(c[3])
        : "r"(a[0]), "r"(a[1]), "r"(a[2]), "r"(a[3]), "r"(b0), "r"(b1));
}

// ---------------------------------------------------------------- tile loader
__device__ __forceinline__ void load_tile(uint32_t sA, uint32_t sB,
    const float* __restrict__ Ab, const float* __restrict__ Bb,
    int lda, int ldb, int k0, int tid)
{
#pragma unroll
    for (int i = 0; i < 8; i++) {
        int idx = tid + i*256;
        int row = idx >> 3;
        int ck  = (idx & 7) << 2;
        uint32_t so = SWZ((uint32_t)(row*128 + ck*4));
        cp16(sA + so, Ab + (size_t)row*lda + k0 + ck);
    }
#pragma unroll
    for (int i = 0; i < 4; i++) {
        int idx = tid + i*256;
        int row = idx >> 3;
        int ck  = (idx & 7) << 2;
        uint32_t so = SWZ((uint32_t)(row*128 + ck*4));
        cp16(sB + so, Bb + (size_t)row*ldb + k0 + ck);
    }
}

// ---------------------------------------------------------------- mma GEMM
// C[bz][m][n] = alpha * sum_k A[bz][m][k] * B[bz][n][k]  (+ bias[n])
// NT gemm, tf32. 256x128 CTA tile, 8 warps (4x2) of 64x64.
// 3-stage cp.async pipeline, ONE __syncthreads per K-iter:
//   wait_group 1 -> sync -> issue loads for it+2 (stage consumed at it-1) -> compute
template<bool CSKIP, bool CK, bool HB, bool CVTA, bool ROUND>
__global__ void __launch_bounds__(256) gemm_tc(
    const float* __restrict__ A, const float* __restrict__ B,
    float* __restrict__ C, const float* __restrict__ bias,
    int K, int lda, int ldb, int ldc, long sA, long sB, long sC, float alpha)
{
    const int bx = blockIdx.x, by = blockIdx.y, bz = blockIdx.z;
    if (CSKIP && bx > 2*by + 1) return;

    extern __shared__ char smem[];
    const uint32_t tb = (smem_u32(smem) + 1023) & ~1023u;
    const int tid = threadIdx.x, wid = tid >> 5, lid = tid & 31;
    const int wm = wid >> 1;       // 4 m-blocks of 64
    const int wn = wid & 1;        // 2 n-blocks of 64

    const float* Ab = A + (size_t)bz*sA + (size_t)by*BM*lda;
    const float* Bb = B + (size_t)bz*sB + (size_t)bx*BN*ldb;
    float* Cb = C + (size_t)bz*sC;
    const int kEnd = CK ? min(K, (by + 1)*BM) : K;
    const int iters = kEnd >> 5;   // >= 8 always

    float acc[4][8][4];
#pragma unroll
    for (int i = 0; i < 4; i++)
#pragma unroll
        for (int j = 0; j < 8; j++)
#pragma unroll
            for (int r = 0; r < 4; r++) acc[i][j][r] = 0.0f;

    const uint32_t aRow  = (uint32_t)((wm*64 + (lid & 15)) * 128);
    const uint32_t aKoff = (uint32_t)((lid >> 4) * 16);
    const uint32_t bRow  = (uint32_t)((wn*64 + (lid & 7) + ((lid >> 4) * 8)) * 128);
    const uint32_t bKoff = (uint32_t)(((lid >> 3) & 1) * 16);

    // prologue: stages 0,1 (data for iters 0,1), one commit group each
#pragma unroll
    for (int s = 0; s < 2; s++) {
        load_tile(tb + s*STAGE_BYTES, tb + s*STAGE_BYTES + A_BYTES,
                  Ab, Bb, lda, ldb, s*BKK, tid);
        CP_COMMIT();
    }

    uint32_t afr[2][4][4], bfr[2][4][4];
    int stage = 0;

    for (int it = 0; it < iters; ++it) {
        CP_WAIT1();          // group for iter `it` complete (1 newer outstanding)
        __syncthreads();     // all warps done reading stage (it-1)%3

        // issue loads for iter it+2 into stage (it+2)%3 == (it-1)%3 (safe now)
        const int nit = it + 2;
        if (nit < iters) {
            const int ls = (stage + 2 >= NSTAGES) ? stage + 2 - NSTAGES : stage + 2;
            load_tile(tb + ls*STAGE_BYTES, tb + ls*STAGE_BYTES + A_BYTES,
                      Ab, Bb, lda, ldb, nit*BKK, tid);
        }
        CP_COMMIT();         // always commit (empty groups complete immediately)

        const uint32_t sAb = tb + stage*STAGE_BYTES;
        const uint32_t sBb = sAb + A_BYTES;

        // preload kc=0 fragments
#pragma unroll
        for (int i = 0; i < 4; i++) {
            uint32_t off = aRow + (uint32_t)(i*16*128) + aKoff;
            ldm_x4(afr[0][i][0], afr[0][i][1], afr[0][i][2], afr[0][i][3],
                   sAb + SWZ(off));
        }
#pragma unroll
        for (int p = 0; p < 4; p++) {
            uint32_t off = bRow + (uint32_t)(p*16*128) + bKoff;
            ldm_x4(bfr[0][p][0], bfr[0][p][1], bfr[0][p][2], bfr[0][p][3],
                   sBb + SWZ(off));
        }

#pragma unroll
        for (int kc = 0; kc < 4; kc++) {
            const int cur = kc & 1, nxt = cur ^ 1;
            if (kc < 3) {
                const uint32_t kb = (uint32_t)((kc + 1) * 32);
#pragma unroll
                for (int i = 0; i < 4; i++) {
                    uint32_t off = aRow + (uint32_t)(i*16*128) + kb + aKoff;
                    ldm_x4(afr[nxt][i][0], afr[nxt][i][1],
                           afr[nxt][i][2], afr[nxt][i][3], sAb + SWZ(off));
                }
#pragma unroll
                for (int p = 0; p < 4; p++) {
                    uint32_t off = bRow + (uint32_t)(p*16*128) + kb + bKoff;
                    ldm_x4(bfr[nxt][p][0], bfr[nxt][p][1],
                           bfr[nxt][p][2], bfr[nxt][p][3], sBb + SWZ(off));
                }
            }
            if (CVTA) {
#pragma unroll
                for (int i = 0; i < 4; i++) {
                    CVT_TF32(afr[cur][i][0]); CVT_TF32(afr[cur][i][1]);
                    CVT_TF32(afr[cur][i][2]); CVT_TF32(afr[cur][i][3]);
                }
            }
#pragma unroll
            for (int i = 0; i < 4; i++)
#pragma unroll
                for (int j = 0; j < 8; j++)
                    mma_m16n8k8(acc[i][j], afr[cur][i],
                                bfr[cur][j >> 1][(j & 1)*2],
                                bfr[cur][j >> 1][(j & 1)*2 + 1]);
        }

        stage = (stage + 1 >= NSTAGES) ? 0 : stage + 1;
    }

    const int rowg = by*BM + wm*64 + (lid >> 2);
    const int colg = bx*BN + wn*64 + (lid & 3)*2;
#pragma unroll
    for (int j = 0; j < 8; j++) {
        const int c = colg + j*8;
        float2 bv = make_float2(0.f, 0.f);
        if (HB) bv = *(const float2*)(bias + c);
#pragma unroll
        for (int i = 0; i < 4; i++) {
            const int r = rowg + i*16;
            float2 v0, v1;
            v0.x = acc[i][j][0]*alpha + bv.x;
            v0.y = acc[i][j][1]*alpha + bv.y;
            v1.x = acc[i][j][2]*alpha + bv.x;
            v1.y = acc[i][j][3]*alpha + bv.y;
            if (ROUND) {
                v0.x = tf32r(v0.x); v0.y = tf32r(v0.y);
                v1.x = tf32r(v1.x); v1.y = tf32r(v1.y);
            }
            *(float2*)(Cb + (size_t)r*ldc + c)     = v0;
            *(float2*)(Cb + (size_t)(r+8)*ldc + c) = v1;
        }
    }
}

// ---------------------------------------------------------------- transpose
__global__ void __launch_bounds__(256) transpose_g(
    const float* __restrict__ in, float* __restrict__ out,
    int ldin, int ldout, long sIn, long sOut)
{
    __shared__ float t[32][33];
    const int b = blockIdx.z;
    in  += (size_t)b * sIn;
    out += (size_t)b * sOut;
    const int x = blockIdx.x * 32;
    const int y = blockIdx.y * 32;
#pragma unroll
    for (int j = threadIdx.y; j < 32; j += 8)
        t[j][threadIdx.x] = tf32r(in[(size_t)(y + j)*ldin + x + threadIdx.x]);
    __syncthreads();
#pragma unroll
    for (int j = threadIdx.y; j < 32; j += 8)
        out[(size_t)(x + j)*ldout + y + threadIdx.x] = t[threadIdx.x][j];
}

// ---------------------------------------------------------------- softmax
// Single-pass register-resident causal softmax: T==2048, 256 threads ->
// exactly 8 elems/thread. 1 read + 1 write of S (was 3 reads + 2 writes).
__global__ __launch_bounds__(256)
void softmax_causal(float* __restrict__ S, int T)
{
    const int i = blockIdx.x;
    const int b = blockIdx.y;
    float* row = S + ((size_t)b*T + i)*T;
    const int L = i + 1;
    const int tid = threadIdx.x;

    __shared__ float red[8];
    __shared__ float bval;

    float v[8];
    float m = -1e30f;
#pragma unroll
    for (int k = 0; k < 8; k++) {
        const int j = tid + k*256;
        v[k] = (j < L) ? row[j] : -1e30f;
        m = fmaxf(m, v[k]);
    }
#pragma unroll
    for (int o = 16; o; o >>= 1) m = fmaxf(m, __shfl_xor_sync(0xffffffffu, m, o));
    if ((tid & 31) == 0) red[tid >> 5] = m;
    __syncthreads();
    if (tid == 0) {
        float mm = red[0];
#pragma unroll
        for (int w = 1; w < 8; w++) mm = fmaxf(mm, red[w]);
        bval = mm;
    }
    __syncthreads();
    m = bval;
    __syncthreads();

    float s = 0.0f;
#pragma unroll
    for (int k = 0; k < 8; k++) {
        const int j = tid + k*256;
        v[k] = (j < L) ? expf(v[k] - m) : 0.0f;
        s += v[k];
    }
#pragma unroll
    for (int o = 16; o; o >>= 1) s += __shfl_xor_sync(0xffffffffu, s, o);
    if ((tid & 31) == 0) red[tid >> 5] = s;
    __syncthreads();
    if (tid == 0) {
        float ss = 0.0f;
#pragma unroll
        for (int w = 0; w < 8; w++) ss += red[w];
        bval = ss;
    }
    __syncthreads();
    const float inv = 1.0f / bval;

    // write tf32-rounded P; zero [L, 256-block-end) for PV's 256-granular k-limit
    const int end = ((i >> 8) + 1) << 8;
#pragma unroll
    for (int k = 0; k < 8; k++) {
        const int j = tid + k*256;
        if (j < L)        row[j] = tf32r(v[k] * inv);
        else if (j < end) row[j] = 0.0f;
    }
}

// ---------------------------------------------------------------- launch
extern "C" void kernel_launch(void* const* d_in, const int* in_sizes, int n_in,
                              void* d_out, int out_size)
{
    (void)in_sizes; (void)n_in; (void)out_size;
    const float* x      = (const float*)d_in[0];
    const float* W_kqv  = (const float*)d_in[1];
    const float* b_kqv  = (const float*)d_in[2];
    const float* W_proj = (const float*)d_in[3];
    const float* b_proj = (const float*)d_in[4];
    float* out = (float*)d_out;

    float *kqv, *S, *O, *Wt, *WtP, *Vt;
    cudaGetSymbolAddress((void**)&kqv, g_kqv);
    cudaGetSymbolAddress((void**)&S,   g_S);
    cudaGetSymbolAddress((void**)&O,   g_O);
    cudaGetSymbolAddress((void**)&Wt,  g_Wt);
    cudaGetSymbolAddress((void**)&WtP, g_WtP);
    cudaGetSymbolAddress((void**)&Vt,  g_Vt);

    const int B = BATCH, T = SEQ, C = CDIM;
    const float scale = 1.0f / sqrtf((float)T);
    const long sBT3C = (long)T*3*C;

    cudaFuncSetAttribute(gemm_tc<false,false,true,true,true>,
        cudaFuncAttributeMaxDynamicSharedMemorySize, SMEM_DYN);
    cudaFuncSetAttribute(gemm_tc<true,false,false,false,false>,
        cudaFuncAttributeMaxDynamicSharedMemorySize, SMEM_DYN);
    cudaFuncSetAttribute(gemm_tc<false,true,false,false,true>,
        cudaFuncAttributeMaxDynamicSharedMemorySize, SMEM_DYN);
    cudaFuncSetAttribute(gemm_tc<false,false,true,false,false>,
        cudaFuncAttributeMaxDynamicSharedMemorySize, SMEM_DYN);

    // 1) Wt = W_kqv^T (tf32-rounded)
    transpose_g<<<dim3(3*C/32, C/32, 1), dim3(32,8)>>>(W_kqv, Wt, 3*C, C, 0, 0);

    // 2) kqv = x @ W_kqv + b_kqv
    gemm_tc<false,false,true,true,true><<<dim3(3*C/BN, (B*T)/BM, 1), 256, SMEM_DYN>>>(
        x, Wt, kqv, b_kqv, C, C, C, 3*C, 0, 0, 0, 1.0f);

    // 3) Vt[b][c][t] = kqv[b*T+t][2C+c]
    transpose_g<<<dim3(C/32, T/32, B), dim3(32,8)>>>(
        kqv + 2*C, Vt, 3*C, T, sBT3C, (long)C*T);

    // 4) S = Q @ K^T * scale (causal block-skip, 256x128 blocks)
    gemm_tc<true,false,false,false,false><<<dim3(T/BN, T/BM, B), 256, SMEM_DYN>>>(
        kqv + C, kqv, S, nullptr, C, 3*C, 3*C, T,
        sBT3C, sBT3C, (long)T*T, scale);

    // 5) causal softmax (single-pass, tf32-rounded P, zeros to 256-block ends)
    softmax_causal<<<dim3(T, B, 1), 256>>>(S, T);

    // 6) O = P @ V (causal k-limit, 256-granular)  <-- ncu-profiled launch
    gemm_tc<false,true,false,false,true><<<dim3(C/BN, T/BM, B), 256, SMEM_DYN>>>(
        S, Vt, O, nullptr, T, T, T, C,
        (long)T*T, (long)C*T, (long)T*C, 1.0f);

    // 7) WtP = W_proj^T
    transpose_g<<<dim3(C/32, C/32, 1), dim3(32,8)>>>(W_proj, WtP, C, C, 0, 0);

    // 8) out = O @ W_proj + b_proj
    gemm_tc<false,false,true,false,false><<<dim3(C/BN, (B*T)/BM, 1), 256, SMEM_DYN>>>(
        O, WtP, out, b_proj, C, C, C, C, 0, 0, 0, 1.0f);
}

// round 10
// speedup vs baseline: 1.1919x; 1.0715x over previous
#include <cuda_runtime.h>
#include <cstdint>
#include <math.h>

// ---------------------------------------------------------------- constants
#define BATCH 8
#define SEQ   2048
#define CDIM  1024

#define BM 256
#define BN 128
#define BKK 32                      // fp32 elems per stage row = 128 bytes
#define NSTAGES 3
#define A_BYTES (BM*128)            // 32KB
#define B_BYTES (BN*128)            // 16KB
#define STAGE_BYTES (A_BYTES + B_BYTES)
#define SMEM_DYN (NSTAGES*STAGE_BYTES + 1024)

#define SWZ(x) ((x) ^ (((x)>>3)&0x70))

// ---------------------------------------------------------------- scratch
__device__ float g_kqv[(size_t)BATCH*SEQ*3*CDIM];  // [B*T, 3C]
__device__ float g_S  [(size_t)BATCH*SEQ*SEQ];     // [B, T, T]
__device__ float g_O  [(size_t)BATCH*SEQ*CDIM];    // [B*T, C]
__device__ float g_Wt [(size_t)3*CDIM*CDIM];       // W_kqv^T  [3C, C]
__device__ float g_WtP[(size_t)CDIM*CDIM];         // W_proj^T [C, C]
__device__ float g_Vt [(size_t)BATCH*CDIM*SEQ];    // V^T per batch [C, T]

// ---------------------------------------------------------------- ptx utils
__device__ __forceinline__ uint32_t smem_u32(const void* p){
    uint32_t a;
    asm("{ .reg .u64 t; cvta.to.shared.u64 t, %1; cvt.u32.u64 %0, t; }"
        : "=r"(a) : "l"(p));
    return a;
}
__device__ __forceinline__ void cp16(uint32_t dst, const void* src){
    asm volatile("cp.async.cg.shared.global [%0], [%1], 16;" :: "r"(dst), "l"(src));
}
// mbarrier pipeline primitives (sm_80/90 PTX, legal on plain sm_103)
#define MB_INIT(a, c) \
    asm volatile("mbarrier.init.shared.b64 [%0], %1;" :: "r"(a), "r"(c) : "memory")
#define MB_ARRIVE(a) \
    asm volatile("mbarrier.arrive.shared.b64 _, [%0];" :: "r"(a) : "memory")
#define CP_MBAR_NOINC(a) \
    asm volatile("cp.async.mbarrier.arrive.noinc.shared.b64 [%0];" :: "r"(a) : "memory")

#define MB_WAIT_PARITY(a, ph) do { \
    uint32_t _m=(uint32_t)(a), _p=(uint32_t)(ph), _d; \
    asm volatile("{\n\t.reg .pred p;\n\t" \
        "mbarrier.try_wait.parity.acquire.cta.shared::cta.b64 p, [%1], %2;\n\t" \
        "selp.b32 %0, 1, 0, p;\n\t}" : "=r"(_d) : "r"(_m), "r"(_p) : "memory"); \
    if (!_d) { \
        asm volatile("{\n\t.reg .pred P1;\n\tWL_%=:\n\t" \
            "mbarrier.try_wait.parity.acquire.cta.shared::cta.b64 P1, [%0], %1, 0x989680;\n\t" \
            "@P1 bra.uni WD_%=;\n\tbra.uni WL_%=;\n\tWD_%=:\n\t}" \
            :: "r"(_m), "r"(_p) : "memory"); \
    } } while(0)

__device__ __forceinline__ void ldm_x4(uint32_t& r0, uint32_t& r1,
                                       uint32_t& r2, uint32_t& r3, uint32_t a){
    asm volatile("ldmatrix.sync.aligned.m8n8.x4.shared.b16 {%0,%1,%2,%3}, [%4];"
        : "=r"(r0), "=r"(r1), "=r"(r2), "=r"(r3) : "r"(a));
}
#define CVT_TF32(x) asm volatile("cvt.rna.tf32.f32 %0, %0;" : "+r"(x))

__device__ __forceinline__ float tf32r(float x){
    uint32_t u = __float_as_uint(x);
    asm("cvt.rna.tf32.f32 %0, %0;" : "+r"(u));
    return __uint_as_float(u);
}

__device__ __forceinline__ void mma_m16n8k8(float* c, const uint32_t* a,
                                            uint32_t b0, uint32_t b1){
    asm volatile(
        "mma.sync.aligned.m16n8k8.row.col.f32.tf32.tf32.f32 "
        "{%0,%1,%2,%3}, {%4,%5,%6,%7}, {%8,%9}, {%0,%1,%2,%3};"
        : "+f"(c[0]), "+f"(c[1]), "+f"(c[2]), "+f"(c[3])
        : "r"(a[0]), "r"(a[1]), "r"(a[2]), "r"(a[3]), "r"(b0), "r"(b1));
}

// ---------------------------------------------------------------- tile loader
__device__ __forceinline__ void load_tile(uint32_t sA, uint32_t sB,
    const float* __restrict__ Ab, const float* __restrict__ Bb,
    int lda, int ldb, int k0, int tid)
{
#pragma unroll
    for (int i = 0; i < 8; i++) {
        int idx = tid + i*256;
        int row = idx >> 3;
        int ck  = (idx & 7) << 2;
        uint32_t so = SWZ((uint32_t)(row*128 + ck*4));
        cp16(sA + so, Ab + (size_t)row*lda + k0 + ck);
    }
#pragma unroll
    for (int i = 0; i < 4; i++) {
        int idx = tid + i*256;
        int row = idx >> 3;
        int ck  = (idx & 7) << 2;
        uint32_t so = SWZ((uint32_t)(row*128 + ck*4));
        cp16(sB + so, Bb + (size_t)row*ldb + k0 + ck);
    }
}

// ---------------------------------------------------------------- mma GEMM
// C[bz][m][n] = alpha * sum_k A[bz][m][k] * B[bz][n][k]  (+ bias[n])
// NT gemm, tf32. 256x128 CTA tile, 8 warps (4x2) of 64x64.
// mbarrier producer/consumer pipeline: NO __syncthreads in the mainloop.
// full[s]: 256 cp.async.mbarrier.arrive.noinc; empty[s]: 256 mbarrier.arrive.
template<bool CSKIP, bool CK, bool HB, bool CVTA, bool ROUND>
__global__ void __launch_bounds__(256) gemm_tc(
    const float* __restrict__ A, const float* __restrict__ B,
    float* __restrict__ C, const float* __restrict__ bias,
    int K, int lda, int ldb, int ldc, long sA, long sB, long sC, float alpha)
{
    const int bx = blockIdx.x, by = blockIdx.y, bz = blockIdx.z;
    if (CSKIP && bx > 2*by + 1) return;

    extern __shared__ char smem[];
    __shared__ uint64_t mbars[2*NSTAGES];   // [full0..2, empty0..2]
    const uint32_t tb = (smem_u32(smem) + 1023) & ~1023u;
    const uint32_t mb = smem_u32(mbars);
    const int tid = threadIdx.x, wid = tid >> 5, lid = tid & 31;
    const int wm = wid >> 1;       // 4 m-blocks of 64
    const int wn = wid & 1;        // 2 n-blocks of 64

    const float* Ab = A + (size_t)bz*sA + (size_t)by*BM*lda;
    const float* Bb = B + (size_t)bz*sB + (size_t)bx*BN*ldb;
    float* Cb = C + (size_t)bz*sC;
    const int kEnd = CK ? min(K, (by + 1)*BM) : K;
    const int iters = kEnd >> 5;   // >= 8 always

    if (tid == 0) {
#pragma unroll
        for (int s = 0; s < NSTAGES; s++) {
            MB_INIT(mb + 8*s, 256);                 // full[s]
            MB_INIT(mb + 8*(NSTAGES + s), 256);     // empty[s]
        }
    }
    __syncthreads();   // the ONLY block-wide barrier before the epilogue

    float acc[4][8][4];
#pragma unroll
    for (int i = 0; i < 4; i++)
#pragma unroll
        for (int j = 0; j < 8; j++)
#pragma unroll
            for (int r = 0; r < 4; r++) acc[i][j][r] = 0.0f;

    const uint32_t aRow  = (uint32_t)((wm*64 + (lid & 15)) * 128);
    const uint32_t aKoff = (uint32_t)((lid >> 4) * 16);
    const uint32_t bRow  = (uint32_t)((wn*64 + (lid & 7) + ((lid >> 4) * 8)) * 128);
    const uint32_t bKoff = (uint32_t)(((lid >> 3) & 1) * 16);

    // prologue: produce iters 0,1 into stages 0,1
#pragma unroll
    for (int s = 0; s < 2; s++) {
        load_tile(tb + s*STAGE_BYTES, tb + s*STAGE_BYTES + A_BYTES,
                  Ab, Bb, lda, ldb, s*BKK, tid);
        CP_MBAR_NOINC(mb + 8*s);
    }

    uint32_t afr[2][4][4], bfr[2][4][4];
    int cstage = 0, cphase = 0;    // consume cursor
    int ephase = 0;                // producer's empty-wait phase

    for (int it = 0; it < iters; ++it) {
        // ---- produce iter it+2 into stage (cstage+2)%3 ----
        const int nit = it + 2;
        if (nit < iters) {
            int ps = cstage + 2; if (ps >= NSTAGES) ps -= NSTAGES;
            if (nit >= NSTAGES) {                   // stage has a prior reader
                MB_WAIT_PARITY(mb + 8*(NSTAGES + ps), ephase);
                if (ps == NSTAGES - 1) ephase ^= 1;
            }
            load_tile(tb + ps*STAGE_BYTES, tb + ps*STAGE_BYTES + A_BYTES,
                      Ab, Bb, lda, ldb, nit*BKK, tid);
            CP_MBAR_NOINC(mb + 8*ps);
        }

        // ---- consume iter it from stage cstage ----
        MB_WAIT_PARITY(mb + 8*cstage, cphase);
        const uint32_t sAb = tb + cstage*STAGE_BYTES;
        const uint32_t sBb = sAb + A_BYTES;

        // preload kc=0 fragments
#pragma unroll
        for (int i = 0; i < 4; i++) {
            uint32_t off = aRow + (uint32_t)(i*16*128) + aKoff;
            ldm_x4(afr[0][i][0], afr[0][i][1], afr[0][i][2], afr[0][i][3],
                   sAb + SWZ(off));
        }
#pragma unroll
        for (int p = 0; p < 4; p++) {
            uint32_t off = bRow + (uint32_t)(p*16*128) + bKoff;
            ldm_x4(bfr[0][p][0], bfr[0][p][1], bfr[0][p][2], bfr[0][p][3],
                   sBb + SWZ(off));
        }

#pragma unroll
        for (int kc = 0; kc < 4; kc++) {
            const int cur = kc & 1, nxt = cur ^ 1;
            if (kc < 3) {
                const uint32_t kb = (uint32_t)((kc + 1) * 32);
#pragma unroll
                for (int i = 0; i < 4; i++) {
                    uint32_t off = aRow + (uint32_t)(i*16*128) + kb + aKoff;
                    ldm_x4(afr[nxt][i][0], afr[nxt][i][1],
                           afr[nxt][i][2], afr[nxt][i][3], sAb + SWZ(off));
                }
#pragma unroll
                for (int p = 0; p < 4; p++) {
                    uint32_t off = bRow + (uint32_t)(p*16*128) + kb + bKoff;
                    ldm_x4(bfr[nxt][p][0], bfr[nxt][p][1],
                           bfr[nxt][p][2], bfr[nxt][p][3], sBb + SWZ(off));
                }
            }
            if (CVTA) {
#pragma unroll
                for (int i = 0; i < 4; i++) {
                    CVT_TF32(afr[cur][i][0]); CVT_TF32(afr[cur][i][1]);
                    CVT_TF32(afr[cur][i][2]); CVT_TF32(afr[cur][i][3]);
                }
            }
#pragma unroll
            for (int i = 0; i < 4; i++)
#pragma unroll
                for (int j = 0; j < 8; j++)
                    mma_m16n8k8(acc[i][j], afr[cur][i],
                                bfr[cur][j >> 1][(j & 1)*2],
                                bfr[cur][j >> 1][(j & 1)*2 + 1]);
        }

        MB_ARRIVE(mb + 8*(NSTAGES + cstage));   // release stage for refill
        if (++cstage == NSTAGES) { cstage = 0; cphase ^= 1; }
    }

    const int rowg = by*BM + wm*64 + (lid >> 2);
    const int colg = bx*BN + wn*64 + (lid & 3)*2;
#pragma unroll
    for (int j = 0; j < 8; j++) {
        const int c = colg + j*8;
        float2 bv = make_float2(0.f, 0.f);
        if (HB) bv = *(const float2*)(bias + c);
#pragma unroll
        for (int i = 0; i < 4; i++) {
            const int r = rowg + i*16;
            float2 v0, v1;
            v0.x = acc[i][j][0]*alpha + bv.x;
            v0.y = acc[i][j][1]*alpha + bv.y;
            v1.x = acc[i][j][2]*alpha + bv.x;
            v1.y = acc[i][j][3]*alpha + bv.y;
            if (ROUND) {
                v0.x = tf32r(v0.x); v0.y = tf32r(v0.y);
                v1.x = tf32r(v1.x); v1.y = tf32r(v1.y);
            }
            *(float2*)(Cb + (size_t)r*ldc + c)     = v0;
            *(float2*)(Cb + (size_t)(r+8)*ldc + c) = v1;
        }
    }
}

// ---------------------------------------------------------------- transpose
__global__ void __launch_bounds__(256) transpose_g(
    const float* __restrict__ in, float* __restrict__ out,
    int ldin, int ldout, long sIn, long sOut)
{
    __shared__ float t[32][33];
    const int b = blockIdx.z;
    in  += (size_t)b * sIn;
    out += (size_t)b * sOut;
    const int x = blockIdx.x * 32;
    const int y = blockIdx.y * 32;
#pragma unroll
    for (int j = threadIdx.y; j < 32; j += 8)
        t[j][threadIdx.x] = tf32r(in[(size_t)(y + j)*ldin + x + threadIdx.x]);
    __syncthreads();
#pragma unroll
    for (int j = threadIdx.y; j < 32; j += 8)
        out[(size_t)(x + j)*ldout + y + threadIdx.x] = t[threadIdx.x][j];
}

// ---------------------------------------------------------------- softmax
// Single-pass register-resident causal softmax (8 elems/thread).
__global__ __launch_bounds__(256)
void softmax_causal(float* __restrict__ S, int T)
{
    const int i = blockIdx.x;
    const int b = blockIdx.y;
    float* row = S + ((size_t)b*T + i)*T;
    const int L = i + 1;
    const int tid = threadIdx.x;

    __shared__ float red[8];
    __shared__ float bval;

    float v[8];
    float m = -1e30f;
#pragma unroll
    for (int k = 0; k < 8; k++) {
        const int j = tid + k*256;
        v[k] = (j < L) ? row[j] : -1e30f;
        m = fmaxf(m, v[k]);
    }
#pragma unroll
    for (int o = 16; o; o >>= 1) m = fmaxf(m, __shfl_xor_sync(0xffffffffu, m, o));
    if ((tid & 31) == 0) red[tid >> 5] = m;
    __syncthreads();
    if (tid == 0) {
        float mm = red[0];
#pragma unroll
        for (int w = 1; w < 8; w++) mm = fmaxf(mm, red[w]);
        bval = mm;
    }
    __syncthreads();
    m = bval;
    __syncthreads();

    float s = 0.0f;
#pragma unroll
    for (int k = 0; k < 8; k++) {
        const int j = tid + k*256;
        v[k] = (j < L) ? expf(v[k] - m) : 0.0f;
        s += v[k];
    }
#pragma unroll
    for (int o = 16; o; o >>= 1) s += __shfl_xor_sync(0xffffffffu, s, o);
    if ((tid & 31) == 0) red[tid >> 5] = s;
    __syncthreads();
    if (tid == 0) {
        float ss = 0.0f;
#pragma unroll
        for (int w = 0; w < 8; w++) ss += red[w];
        bval = ss;
    }
    __syncthreads();
    const float inv = 1.0f / bval;

    const int end = ((i >> 8) + 1) << 8;
#pragma unroll
    for (int k = 0; k < 8; k++) {
        const int j = tid + k*256;
        if (j < L)        row[j] = tf32r(v[k] * inv);
        else if (j < end) row[j] = 0.0f;
    }
}

// ---------------------------------------------------------------- launch
extern "C" void kernel_launch(void* const* d_in, const int* in_sizes, int n_in,
                              void* d_out, int out_size)
{
    (void)in_sizes; (void)n_in; (void)out_size;
    const float* x      = (const float*)d_in[0];
    const float* W_kqv  = (const float*)d_in[1];
    const float* b_kqv  = (const float*)d_in[2];
    const float* W_proj = (const float*)d_in[3];
    const float* b_proj = (const float*)d_in[4];
    float* out = (float*)d_out;

    float *kqv, *S, *O, *Wt, *WtP, *Vt;
    cudaGetSymbolAddress((void**)&kqv, g_kqv);
    cudaGetSymbolAddress((void**)&S,   g_S);
    cudaGetSymbolAddress((void**)&O,   g_O);
    cudaGetSymbolAddress((void**)&Wt,  g_Wt);
    cudaGetSymbolAddress((void**)&WtP, g_WtP);
    cudaGetSymbolAddress((void**)&Vt,  g_Vt);

    const int B = BATCH, T = SEQ, C = CDIM;
    const float scale = 1.0f / sqrtf((float)T);
    const long sBT3C = (long)T*3*C;

    cudaFuncSetAttribute(gemm_tc<false,false,true,true,true>,
        cudaFuncAttributeMaxDynamicSharedMemorySize, SMEM_DYN);
    cudaFuncSetAttribute(gemm_tc<true,false,false,false,false>,
        cudaFuncAttributeMaxDynamicSharedMemorySize, SMEM_DYN);
    cudaFuncSetAttribute(gemm_tc<false,true,false,false,true>,
        cudaFuncAttributeMaxDynamicSharedMemorySize, SMEM_DYN);
    cudaFuncSetAttribute(gemm_tc<false,false,true,false,false>,
        cudaFuncAttributeMaxDynamicSharedMemorySize, SMEM_DYN);

    // 1) Wt = W_kqv^T (tf32-rounded)
    transpose_g<<<dim3(3*C/32, C/32, 1), dim3(32,8)>>>(W_kqv, Wt, 3*C, C, 0, 0);

    // 2) kqv = x @ W_kqv + b_kqv
    gemm_tc<false,false,true,true,true><<<dim3(3*C/BN, (B*T)/BM, 1), 256, SMEM_DYN>>>(
        x, Wt, kqv, b_kqv, C, C, C, 3*C, 0, 0, 0, 1.0f);

    // 3) Vt[b][c][t] = kqv[b*T+t][2C+c]
    transpose_g<<<dim3(C/32, T/32, B), dim3(32,8)>>>(
        kqv + 2*C, Vt, 3*C, T, sBT3C, (long)C*T);

    // 4) S = Q @ K^T * scale (causal block-skip, 256x128 blocks)
    gemm_tc<true,false,false,false,false><<<dim3(T/BN, T/BM, B), 256, SMEM_DYN>>>(
        kqv + C, kqv, S, nullptr, C, 3*C, 3*C, T,
        sBT3C, sBT3C, (long)T*T, scale);

    // 5) causal softmax (single-pass, tf32-rounded P, zeros to 256-block ends)
    softmax_causal<<<dim3(T, B, 1), 256>>>(S, T);

    // 6) O = P @ V (causal k-limit, 256-granular)  <-- ncu-profiled launch
    gemm_tc<false,true,false,false,true><<<dim3(C/BN, T/BM, B), 256, SMEM_DYN>>>(
        S, Vt, O, nullptr, T, T, T, C,
        (long)T*T, (long)C*T, (long)T*C, 1.0f);

    // 7) WtP = W_proj^T
    transpose_g<<<dim3(C/32, C/32, 1), dim3(32,8)>>>(W_proj, WtP, C, C, 0, 0);

    // 8) out = O @ W_proj + b_proj
    gemm_tc<false,false,true,false,false><<<dim3(C/BN, (B*T)/BM, 1), 256, SMEM_DYN>>>(
        O, WtP, out, b_proj, C, C, C, C, 0, 0, 0, 1.0f);
}

// round 11
// speedup vs baseline: 1.2447x; 1.0443x over previous
#include <cuda_runtime.h>
#include <cstdint>
#include <math.h>

// ---------------------------------------------------------------- constants
#define BATCH 8
#define SEQ   2048
#define CDIM  1024

#define BM 256
#define BN 128
#define NSTAGES 2
#define A_BYTES 32768               // 256 rows x 128B (32 tf32)
#define B_BYTES 16384               // 128 rows x 128B
#define HALF_BYTES (A_BYTES + B_BYTES)      // 48KB: one 32-K sub-tile
#define STAGE_BYTES (2*HALF_BYTES)          // 96KB: one 64-K mega-stage
#define SMEM_DYN (NSTAGES*STAGE_BYTES + 1024)

#define SWZ(x) ((x) ^ (((x)>>3)&0x70))

// ---------------------------------------------------------------- scratch
__device__ float g_kqv[(size_t)BATCH*SEQ*3*CDIM];  // [B*T, 3C]
__device__ float g_S  [(size_t)BATCH*SEQ*SEQ];     // [B, T, T]
__device__ float g_O  [(size_t)BATCH*SEQ*CDIM];    // [B*T, C]
__device__ float g_Wt [(size_t)3*CDIM*CDIM];       // W_kqv^T  [3C, C]
__device__ float g_WtP[(size_t)CDIM*CDIM];         // W_proj^T [C, C]
__device__ float g_Vt [(size_t)BATCH*CDIM*SEQ];    // V^T per batch [C, T]

// ---------------------------------------------------------------- ptx utils
__device__ __forceinline__ uint32_t smem_u32(const void* p){
    uint32_t a;
    asm("{ .reg .u64 t; cvta.to.shared.u64 t, %1; cvt.u32.u64 %0, t; }"
        : "=r"(a) : "l"(p));
    return a;
}
__device__ __forceinline__ void cp16(uint32_t dst, const void* src){
    asm volatile("cp.async.cg.shared.global [%0], [%1], 16;" :: "r"(dst), "l"(src));
}
#define MB_INIT(a, c) \
    asm volatile("mbarrier.init.shared.b64 [%0], %1;" :: "r"(a), "r"(c) : "memory")
#define MB_ARRIVE(a) \
    asm volatile("mbarrier.arrive.shared.b64 _, [%0];" :: "r"(a) : "memory")
#define CP_MBAR_NOINC(a) \
    asm volatile("cp.async.mbarrier.arrive.noinc.shared.b64 [%0];" :: "r"(a) : "memory")

#define MB_WAIT_PARITY(a, ph) do { \
    uint32_t _m=(uint32_t)(a), _p=(uint32_t)(ph), _d; \
    asm volatile("{\n\t.reg .pred p;\n\t" \
        "mbarrier.try_wait.parity.acquire.cta.shared::cta.b64 p, [%1], %2;\n\t" \
        "selp.b32 %0, 1, 0, p;\n\t}" : "=r"(_d) : "r"(_m), "r"(_p) : "memory"); \
    if (!_d) { \
        asm volatile("{\n\t.reg .pred P1;\n\tWL_%=:\n\t" \
            "mbarrier.try_wait.parity.acquire.cta.shared::cta.b64 P1, [%0], %1, 0x989680;\n\t" \
            "@P1 bra.uni WD_%=;\n\tbra.uni WL_%=;\n\tWD_%=:\n\t}" \
            :: "r"(_m), "r"(_p) : "memory"); \
    } } while(0)

__device__ __forceinline__ void ldm_x4(uint32_t& r0, uint32_t& r1,
                                       uint32_t& r2, uint32_t& r3, uint32_t a){
    asm volatile("ldmatrix.sync.aligned.m8n8.x4.shared.b16 {%0,%1,%2,%3}, [%4];"
        : "=r"(r0), "=r"(r1), "=r"(r2), "=r"(r3) : "r"(a));
}
#define CVT_TF32(x) asm volatile("cvt.rna.tf32.f32 %0, %0;" : "+r"(x))

__device__ __forceinline__ float tf32r(float x){
    uint32_t u = __float_as_uint(x);
    asm("cvt.rna.tf32.f32 %0, %0;" : "+r"(u));
    return __uint_as_float(u);
}

__device__ __forceinline__ void mma_m16n8k8(float* c, const uint32_t* a,
                                            uint32_t b0, uint32_t b1){
    asm volatile(
        "mma.sync.aligned.m16n8k8.row.col.f32.tf32.tf32.f32 "
        "{%0,%1,%2,%3}, {%4,%5,%6,%7}, {%8,%9}, {%0,%1,%2,%3};"
        : "+f"(c[0]), "+f"(c[1]), "+f"(c[2]), "+f"(c[3])
        : "r"(a[0]), "r"(a[1]), "r"(a[2]), "r"(a[3]), "r"(b0), "r"(b1));
}

// ---------------------------------------------------------------- tile loader
// one 32-K sub-tile: A 256x128B (8 cp16/thread), B 128x128B (4 cp16/thread)
__device__ __forceinline__ void load_half(uint32_t sA, uint32_t sB,
    const float* __restrict__ Ab, const float* __restrict__ Bb,
    int lda, int ldb, int k0, int tid)
{
#pragma unroll
    for (int i = 0; i < 8; i++) {
        int idx = tid + i*256;
        int row = idx >> 3;
        int ck  = (idx & 7) << 2;
        uint32_t so = SWZ((uint32_t)(row*128 + ck*4));
        cp16(sA + so, Ab + (size_t)row*lda + k0 + ck);
    }
#pragma unroll
    for (int i = 0; i < 4; i++) {
        int idx = tid + i*256;
        int row = idx >> 3;
        int ck  = (idx & 7) << 2;
        uint32_t so = SWZ((uint32_t)(row*128 + ck*4));
        cp16(sB + so, Bb + (size_t)row*ldb + k0 + ck);
    }
}

// ---------------------------------------------------------------- mma GEMM
// C[bz][m][n] = alpha * sum_k A[bz][m][k]*B[bz][n][k] (+bias[n]). NT, tf32.
// 256x128 CTA tile, 8 warps (4x2) of 64x64. mbarrier pipeline with 64-K
// mega-stages (2 sub-tiles per barrier): one full-wait per 256 MMAs.
// Causal GEMMs run rows in reverse (heavy tiles launch first).
template<bool CSKIP, bool CK, bool HB, bool CVTA, bool ROUND>
__global__ void __launch_bounds__(256) gemm_tc(
    const float* __restrict__ A, const float* __restrict__ B,
    float* __restrict__ C, const float* __restrict__ bias,
    int K, int lda, int ldb, int ldc, long sA, long sB, long sC, float alpha)
{
    const int bx = blockIdx.x, bz = blockIdx.z;
    const int by = (CSKIP || CK) ? ((int)gridDim.y - 1 - (int)blockIdx.y)
                                 : (int)blockIdx.y;
    if (CSKIP && bx > 2*by + 1) return;

    extern __shared__ char smem[];
    __shared__ uint64_t mbars[2*NSTAGES];   // full0,full1,empty0,empty1
    const uint32_t tb = (smem_u32(smem) + 1023) & ~1023u;
    const uint32_t mb = smem_u32(mbars);
    const int tid = threadIdx.x, wid = tid >> 5, lid = tid & 31;
    const int wm = wid >> 1;       // 4 m-blocks of 64
    const int wn = wid & 1;        // 2 n-blocks of 64

    const float* Ab = A + (size_t)bz*sA + (size_t)by*BM*lda;
    const float* Bb = B + (size_t)bz*sB + (size_t)bx*BN*ldb;
    float* Cb = C + (size_t)bz*sC;
    const int kEnd = CK ? min(K, (by + 1)*BM) : K;
    const int iters = kEnd >> 6;   // 64-K mega-iters, >= 4 always

    if (tid == 0) {
#pragma unroll
        for (int s = 0; s < NSTAGES; s++) {
            MB_INIT(mb + 8*s, 256);                 // full[s]
            MB_INIT(mb + 8*(NSTAGES + s), 256);     // empty[s]
        }
    }
    __syncthreads();

    float acc[4][8][4];
#pragma unroll
    for (int i = 0; i < 4; i++)
#pragma unroll
        for (int j = 0; j < 8; j++)
#pragma unroll
            for (int r = 0; r < 4; r++) acc[i][j][r] = 0.0f;

    const uint32_t aRow  = (uint32_t)((wm*64 + (lid & 15)) * 128);
    const uint32_t aKoff = (uint32_t)((lid >> 4) * 16);
    const uint32_t bRow  = (uint32_t)((wn*64 + (lid & 7) + ((lid >> 4) * 8)) * 128);
    const uint32_t bKoff = (uint32_t)(((lid >> 3) & 1) * 16);

    // prologue: produce iter 0 into stage 0
    load_half(tb,              tb + A_BYTES,              Ab, Bb, lda, ldb, 0,  tid);
    load_half(tb + HALF_BYTES, tb + HALF_BYTES + A_BYTES, Ab, Bb, lda, ldb, 32, tid);
    CP_MBAR_NOINC(mb);

    uint32_t afr[2][4][4], bfr[2][4][4];

    for (int it = 0; it < iters; ++it) {
        // ---- produce iter it+1 into stage (it+1)&1 ----
        const int nit = it + 1;
        if (nit < iters) {
            const int ps = nit & 1;
            if (nit >= 2)
                MB_WAIT_PARITY(mb + 8*(NSTAGES + ps), ((nit - 2) >> 1) & 1);
            const uint32_t st = tb + ps*STAGE_BYTES;
            load_half(st,              st + A_BYTES,
                      Ab, Bb, lda, ldb, nit*64,      tid);
            load_half(st + HALF_BYTES, st + HALF_BYTES + A_BYTES,
                      Ab, Bb, lda, ldb, nit*64 + 32, tid);
            CP_MBAR_NOINC(mb + 8*ps);
        }

        // ---- consume iter it from stage it&1 ----
        const int cs = it & 1;
        MB_WAIT_PARITY(mb + 8*cs, (it >> 1) & 1);
        const uint32_t sst = tb + cs*STAGE_BYTES;

        // preload chunk q=0 fragments
        {
#pragma unroll
            for (int i = 0; i < 4; i++)
                ldm_x4(afr[0][i][0], afr[0][i][1], afr[0][i][2], afr[0][i][3],
                       sst + SWZ(aRow + (uint32_t)(i*16*128) + aKoff));
#pragma unroll
            for (int p = 0; p < 4; p++)
                ldm_x4(bfr[0][p][0], bfr[0][p][1], bfr[0][p][2], bfr[0][p][3],
                       sst + A_BYTES + SWZ(bRow + (uint32_t)(p*16*128) + bKoff));
        }

#pragma unroll
        for (int q = 0; q < 8; q++) {
            const int cur = q & 1, nxt = cur ^ 1;
            if (q < 7) {
                const uint32_t hb = sst + (uint32_t)(((q+1) >> 2) * HALF_BYTES);
                const uint32_t kb = (uint32_t)(((q+1) & 3) * 32);
#pragma unroll
                for (int i = 0; i < 4; i++)
                    ldm_x4(afr[nxt][i][0], afr[nxt][i][1],
                           afr[nxt][i][2], afr[nxt][i][3],
                           hb + SWZ(aRow + (uint32_t)(i*16*128) + kb + aKoff));
#pragma unroll
                for (int p = 0; p < 4; p++)
                    ldm_x4(bfr[nxt][p][0], bfr[nxt][p][1],
                           bfr[nxt][p][2], bfr[nxt][p][3],
                           hb + A_BYTES + SWZ(bRow + (uint32_t)(p*16*128) + kb + bKoff));
            }
            if (CVTA) {
#pragma unroll
                for (int i = 0; i < 4; i++) {
                    CVT_TF32(afr[cur][i][0]); CVT_TF32(afr[cur][i][1]);
                    CVT_TF32(afr[cur][i][2]); CVT_TF32(afr[cur][i][3]);
                }
            }
#pragma unroll
            for (int i = 0; i < 4; i++)
#pragma unroll
                for (int j = 0; j < 8; j++)
                    mma_m16n8k8(acc[i][j], afr[cur][i],
                                bfr[cur][j >> 1][(j & 1)*2],
                                bfr[cur][j >> 1][(j & 1)*2 + 1]);
        }

        MB_ARRIVE(mb + 8*(NSTAGES + cs));   // release mega-stage
    }

    const int rowg = by*BM + wm*64 + (lid >> 2);
    const int colg = bx*BN + wn*64 + (lid & 3)*2;
#pragma unroll
    for (int j = 0; j < 8; j++) {
        const int c = colg + j*8;
        float2 bv = make_float2(0.f, 0.f);
        if (HB) bv = *(const float2*)(bias + c);
#pragma unroll
        for (int i = 0; i < 4; i++) {
            const int r = rowg + i*16;
            float2 v0, v1;
            v0.x = acc[i][j][0]*alpha + bv.x;
            v0.y = acc[i][j][1]*alpha + bv.y;
            v1.x = acc[i][j][2]*alpha + bv.x;
            v1.y = acc[i][j][3]*alpha + bv.y;
            if (ROUND) {
                v0.x = tf32r(v0.x); v0.y = tf32r(v0.y);
                v1.x = tf32r(v1.x); v1.y = tf32r(v1.y);
            }
            *(float2*)(Cb + (size_t)r*ldc + c)     = v0;
            *(float2*)(Cb + (size_t)(r+8)*ldc + c) = v1;
        }
    }
}

// ---------------------------------------------------------------- transpose
__global__ void __launch_bounds__(256) transpose_g(
    const float* __restrict__ in, float* __restrict__ out,
    int ldin, int ldout, long sIn, long sOut)
{
    __shared__ float t[32][33];
    const int b = blockIdx.z;
    in  += (size_t)b * sIn;
    out += (size_t)b * sOut;
    const int x = blockIdx.x * 32;
    const int y = blockIdx.y * 32;
#pragma unroll
    for (int j = threadIdx.y; j < 32; j += 8)
        t[j][threadIdx.x] = tf32r(in[(size_t)(y + j)*ldin + x + threadIdx.x]);
    __syncthreads();
#pragma unroll
    for (int j = threadIdx.y; j < 32; j += 8)
        out[(size_t)(x + j)*ldout + y + threadIdx.x] = t[threadIdx.x][j];
}

// ---------------------------------------------------------------- softmax
// Single-pass register-resident causal softmax (8 elems/thread).
__global__ __launch_bounds__(256)
void softmax_causal(float* __restrict__ S, int T)
{
    const int i = blockIdx.x;
    const int b = blockIdx.y;
    float* row = S + ((size_t)b*T + i)*T;
    const int L = i + 1;
    const int tid = threadIdx.x;

    __shared__ float red[8];
    __shared__ float bval;

    float v[8];
    float m = -1e30f;
#pragma unroll
    for (int k = 0; k < 8; k++) {
        const int j = tid + k*256;
        v[k] = (j < L) ? row[j] : -1e30f;
        m = fmaxf(m, v[k]);
    }
#pragma unroll
    for (int o = 16; o; o >>= 1) m = fmaxf(m, __shfl_xor_sync(0xffffffffu, m, o));
    if ((tid & 31) == 0) red[tid >> 5] = m;
    __syncthreads();
    if (tid == 0) {
        float mm = red[0];
#pragma unroll
        for (int w = 1; w < 8; w++) mm = fmaxf(mm, red[w]);
        bval = mm;
    }
    __syncthreads();
    m = bval;
    __syncthreads();

    float s = 0.0f;
#pragma unroll
    for (int k = 0; k < 8; k++) {
        const int j = tid + k*256;
        v[k] = (j < L) ? expf(v[k] - m) : 0.0f;
        s += v[k];
    }
#pragma unroll
    for (int o = 16; o; o >>= 1) s += __shfl_xor_sync(0xffffffffu, s, o);
    if ((tid & 31) == 0) red[tid >> 5] = s;
    __syncthreads();
    if (tid == 0) {
        float ss = 0.0f;
#pragma unroll
        for (int w = 0; w < 8; w++) ss += red[w];
        bval = ss;
    }
    __syncthreads();
    const float inv = 1.0f / bval;

    const int end = ((i >> 8) + 1) << 8;
#pragma unroll
    for (int k = 0; k < 8; k++) {
        const int j = tid + k*256;
        if (j < L)        row[j] = tf32r(v[k] * inv);
        else if (j < end) row[j] = 0.0f;
    }
}

// ---------------------------------------------------------------- launch
extern "C" void kernel_launch(void* const* d_in, const int* in_sizes, int n_in,
                              void* d_out, int out_size)
{
    (void)in_sizes; (void)n_in; (void)out_size;
    const float* x      = (const float*)d_in[0];
    const float* W_kqv  = (const float*)d_in[1];
    const float* b_kqv  = (const float*)d_in[2];
    const float* W_proj = (const float*)d_in[3];
    const float* b_proj = (const float*)d_in[4];
    float* out = (float*)d_out;

    float *kqv, *S, *O, *Wt, *WtP, *Vt;
    cudaGetSymbolAddress((void**)&kqv, g_kqv);
    cudaGetSymbolAddress((void**)&S,   g_S);
    cudaGetSymbolAddress((void**)&O,   g_O);
    cudaGetSymbolAddress((void**)&Wt,  g_Wt);
    cudaGetSymbolAddress((void**)&WtP, g_WtP);
    cudaGetSymbolAddress((void**)&Vt,  g_Vt);

    const int B = BATCH, T = SEQ, C = CDIM;
    const float scale = 1.0f / sqrtf((float)T);
    const long sBT3C = (long)T*3*C;

    cudaFuncSetAttribute(gemm_tc<false,false,true,true,true>,
        cudaFuncAttributeMaxDynamicSharedMemorySize, SMEM_DYN);
    cudaFuncSetAttribute(gemm_tc<true,false,false,false,false>,
        cudaFuncAttributeMaxDynamicSharedMemorySize, SMEM_DYN);
    cudaFuncSetAttribute(gemm_tc<false,true,false,false,true>,
        cudaFuncAttributeMaxDynamicSharedMemorySize, SMEM_DYN);
    cudaFuncSetAttribute(gemm_tc<false,false,true,false,false>,
        cudaFuncAttributeMaxDynamicSharedMemorySize, SMEM_DYN);

    // 1) Wt = W_kqv^T (tf32-rounded)
    transpose_g<<<dim3(3*C/32, C/32, 1), dim3(32,8)>>>(W_kqv, Wt, 3*C, C, 0, 0);

    // 2) kqv = x @ W_kqv + b_kqv
    gemm_tc<false,false,true,true,true><<<dim3(3*C/BN, (B*T)/BM, 1), 256, SMEM_DYN>>>(
        x, Wt, kqv, b_kqv, C, C, C, 3*C, 0, 0, 0, 1.0f);

    // 3) Vt[b][c][t] = kqv[b*T+t][2C+c]
    transpose_g<<<dim3(C/32, T/32, B), dim3(32,8)>>>(
        kqv + 2*C, Vt, 3*C, T, sBT3C, (long)C*T);

    // 4) S = Q @ K^T * scale (causal block-skip, rows reversed)
    gemm_tc<true,false,false,false,false><<<dim3(T/BN, T/BM, B), 256, SMEM_DYN>>>(
        kqv + C, kqv, S, nullptr, C, 3*C, 3*C, T,
        sBT3C, sBT3C, (long)T*T, scale);

    // 5) causal softmax (single-pass, tf32-rounded P, zeros to 256-block ends)
    softmax_causal<<<dim3(T, B, 1), 256>>>(S, T);

    // 6) O = P @ V (causal k-limit, heavy rows first)  <-- ncu-profiled launch
    gemm_tc<false,true,false,false,true><<<dim3(C/BN, T/BM, B), 256, SMEM_DYN>>>(
        S, Vt, O, nullptr, T, T, T, C,
        (long)T*T, (long)C*T, (long)T*C, 1.0f);

    // 7) WtP = W_proj^T
    transpose_g<<<dim3(C/32, C/32, 1), dim3(32,8)>>>(W_proj, WtP, C, C, 0, 0);

    // 8) out = O @ W_proj + b_proj
    gemm_tc<false,false,true,false,false><<<dim3(C/BN, (B*T)/BM, 1), 256, SMEM_DYN>>>(
        O, WtP, out, b_proj, C, C, C, C, 0, 0, 0, 1.0f);
}

// round 12
// speedup vs baseline: 1.2668x; 1.0177x over previous
#include <cuda_runtime.h>
#include <cstdint>
#include <math.h>

// ---------------------------------------------------------------- constants
#define BATCH 8
#define SEQ   2048
#define CDIM  1024

#define BM 256
#define BN 128
#define NSTAGES 2
#define A_BYTES 32768               // 256 rows x 128B (32 tf32)
#define B_BYTES 16384               // 128 rows x 128B
#define HALF_BYTES (A_BYTES + B_BYTES)      // 48KB: one 32-K sub-tile
#define STAGE_BYTES (2*HALF_BYTES)          // 96KB: one 64-K mega-stage
#define SMEM_DYN (NSTAGES*STAGE_BYTES + 1024)

#define SWZ(x) ((x) ^ (((x)>>3)&0x70))

// ---------------------------------------------------------------- scratch
__device__ float g_X  [(size_t)BATCH*SEQ*CDIM];    // tf32-rounded x
__device__ float g_kqv[(size_t)BATCH*SEQ*3*CDIM];  // [B*T, 3C]
__device__ float g_S  [(size_t)BATCH*SEQ*SEQ];     // [B, T, T]
__device__ float g_O  [(size_t)BATCH*SEQ*CDIM];    // [B*T, C]
__device__ float g_Wt [(size_t)3*CDIM*CDIM];       // W_kqv^T  [3C, C]
__device__ float g_WtP[(size_t)CDIM*CDIM];         // W_proj^T [C, C]
__device__ float g_Vt [(size_t)BATCH*CDIM*SEQ];    // V^T per batch [C, T]

// ---------------------------------------------------------------- ptx utils
__device__ __forceinline__ uint32_t smem_u32(const void* p){
    uint32_t a;
    asm("{ .reg .u64 t; cvta.to.shared.u64 t, %1; cvt.u32.u64 %0, t; }"
        : "=r"(a) : "l"(p));
    return a;
}
__device__ __forceinline__ void cp16(uint32_t dst, const void* src){
    asm volatile("cp.async.cg.shared.global [%0], [%1], 16;" :: "r"(dst), "l"(src));
}
#define MB_INIT(a, c) \
    asm volatile("mbarrier.init.shared.b64 [%0], %1;" :: "r"(a), "r"(c) : "memory")
#define MB_ARRIVE(a) \
    asm volatile("mbarrier.arrive.shared.b64 _, [%0];" :: "r"(a) : "memory")
#define CP_MBAR_NOINC(a) \
    asm volatile("cp.async.mbarrier.arrive.noinc.shared.b64 [%0];" :: "r"(a) : "memory")

#define MB_WAIT_PARITY(a, ph) do { \
    uint32_t _m=(uint32_t)(a), _p=(uint32_t)(ph), _d; \
    asm volatile("{\n\t.reg .pred p;\n\t" \
        "mbarrier.try_wait.parity.acquire.cta.shared::cta.b64 p, [%1], %2;\n\t" \
        "selp.b32 %0, 1, 0, p;\n\t}" : "=r"(_d) : "r"(_m), "r"(_p) : "memory"); \
    if (!_d) { \
        asm volatile("{\n\t.reg .pred P1;\n\tWL_%=:\n\t" \
            "mbarrier.try_wait.parity.acquire.cta.shared::cta.b64 P1, [%0], %1, 0x989680;\n\t" \
            "@P1 bra.uni WD_%=;\n\tbra.uni WL_%=;\n\tWD_%=:\n\t}" \
            :: "r"(_m), "r"(_p) : "memory"); \
    } } while(0)

__device__ __forceinline__ void ldm_x4(uint32_t& r0, uint32_t& r1,
                                       uint32_t& r2, uint32_t& r3, uint32_t a){
    asm volatile("ldmatrix.sync.aligned.m8n8.x4.shared.b16 {%0,%1,%2,%3}, [%4];"
        : "=r"(r0), "=r"(r1), "=r"(r2), "=r"(r3) : "r"(a));
}

__device__ __forceinline__ float tf32r(float x){
    uint32_t u = __float_as_uint(x);
    asm("cvt.rna.tf32.f32 %0, %0;" : "+r"(u));
    return __uint_as_float(u);
}

__device__ __forceinline__ void mma_m16n8k8(float* c, const uint32_t* a,
                                            uint32_t b0, uint32_t b1){
    asm volatile(
        "mma.sync.aligned.m16n8k8.row.col.f32.tf32.tf32.f32 "
        "{%0,%1,%2,%3}, {%4,%5,%6,%7}, {%8,%9}, {%0,%1,%2,%3};"
        : "+f"(c[0]), "+f"(c[1]), "+f"(c[2]), "+f"(c[3])
        : "r"(a[0]), "r"(a[1]), "r"(a[2]), "r"(a[3]), "r"(b0), "r"(b1));
}

// ---------------------------------------------------------------- tile loader
__device__ __forceinline__ void load_half(uint32_t sA, uint32_t sB,
    const float* __restrict__ Ab, const float* __restrict__ Bb,
    int lda, int ldb, int k0, int tid)
{
#pragma unroll
    for (int i = 0; i < 8; i++) {
        int idx = tid + i*256;
        int row = idx >> 3;
        int ck  = (idx & 7) << 2;
        uint32_t so = SWZ((uint32_t)(row*128 + ck*4));
        cp16(sA + so, Ab + (size_t)row*lda + k0 + ck);
    }
#pragma unroll
    for (int i = 0; i < 4; i++) {
        int idx = tid + i*256;
        int row = idx >> 3;
        int ck  = (idx & 7) << 2;
        uint32_t so = SWZ((uint32_t)(row*128 + ck*4));
        cp16(sB + so, Bb + (size_t)row*ldb + k0 + ck);
    }
}

// ---------------------------------------------------------------- mma GEMM
// C[bz][m][n] = alpha * sum_k A[bz][m][k]*B[bz][n][k] (+bias[n]). NT, tf32.
// 256x128 CTA tile, 8 warps (4x2) of 64x64. mbarrier pipeline with 64-K
// mega-stages. All inputs pre-rounded to tf32 -> no CVT in mainloop.
template<bool CSKIP, bool CK, bool HB, bool ROUND>
__global__ void __launch_bounds__(256) gemm_tc(
    const float* __restrict__ A, const float* __restrict__ B,
    float* __restrict__ C, const float* __restrict__ bias,
    int K, int lda, int ldb, int ldc, long sA, long sB, long sC, float alpha)
{
    const int bx = blockIdx.x, bz = blockIdx.z;
    const int by = (CSKIP || CK) ? ((int)gridDim.y - 1 - (int)blockIdx.y)
                                 : (int)blockIdx.y;
    if (CSKIP && bx > 2*by + 1) return;

    extern __shared__ char smem[];
    __shared__ uint64_t mbars[2*NSTAGES];   // full0,full1,empty0,empty1
    const uint32_t tb = (smem_u32(smem) + 1023) & ~1023u;
    const uint32_t mb = smem_u32(mbars);
    const int tid = threadIdx.x, wid = tid >> 5, lid = tid & 31;
    const int wm = wid >> 1;       // 4 m-blocks of 64
    const int wn = wid & 1;        // 2 n-blocks of 64

    const float* Ab = A + (size_t)bz*sA + (size_t)by*BM*lda;
    const float* Bb = B + (size_t)bz*sB + (size_t)bx*BN*ldb;
    float* Cb = C + (size_t)bz*sC;
    const int kEnd = CK ? min(K, (by + 1)*BM) : K;
    const int iters = kEnd >> 6;   // 64-K mega-iters, >= 4 always

    if (tid == 0) {
#pragma unroll
        for (int s = 0; s < NSTAGES; s++) {
            MB_INIT(mb + 8*s, 256);                 // full[s]
            MB_INIT(mb + 8*(NSTAGES + s), 256);     // empty[s]
        }
    }
    __syncthreads();

    float acc[4][8][4];
#pragma unroll
    for (int i = 0; i < 4; i++)
#pragma unroll
        for (int j = 0; j < 8; j++)
#pragma unroll
            for (int r = 0; r < 4; r++) acc[i][j][r] = 0.0f;

    const uint32_t aRow  = (uint32_t)((wm*64 + (lid & 15)) * 128);
    const uint32_t aKoff = (uint32_t)((lid >> 4) * 16);
    const uint32_t bRow  = (uint32_t)((wn*64 + (lid & 7) + ((lid >> 4) * 8)) * 128);
    const uint32_t bKoff = (uint32_t)(((lid >> 3) & 1) * 16);

    // prologue: produce iter 0 into stage 0
    load_half(tb,              tb + A_BYTES,              Ab, Bb, lda, ldb, 0,  tid);
    load_half(tb + HALF_BYTES, tb + HALF_BYTES + A_BYTES, Ab, Bb, lda, ldb, 32, tid);
    CP_MBAR_NOINC(mb);

    uint32_t afr[2][4][4], bfr[2][4][4];

    for (int it = 0; it < iters; ++it) {
        // ---- produce iter it+1 into stage (it+1)&1 ----
        const int nit = it + 1;
        if (nit < iters) {
            const int ps = nit & 1;
            if (nit >= 2)
                MB_WAIT_PARITY(mb + 8*(NSTAGES + ps), ((nit - 2) >> 1) & 1);
            const uint32_t st = tb + ps*STAGE_BYTES;
            load_half(st,              st + A_BYTES,
                      Ab, Bb, lda, ldb, nit*64,      tid);
            load_half(st + HALF_BYTES, st + HALF_BYTES + A_BYTES,
                      Ab, Bb, lda, ldb, nit*64 + 32, tid);
            CP_MBAR_NOINC(mb + 8*ps);
        }

        // ---- consume iter it from stage it&1 ----
        const int cs = it & 1;
        MB_WAIT_PARITY(mb + 8*cs, (it >> 1) & 1);
        const uint32_t sst = tb + cs*STAGE_BYTES;

        // preload chunk q=0 fragments
        {
#pragma unroll
            for (int i = 0; i < 4; i++)
                ldm_x4(afr[0][i][0], afr[0][i][1], afr[0][i][2], afr[0][i][3],
                       sst + SWZ(aRow + (uint32_t)(i*16*128) + aKoff));
#pragma unroll
            for (int p = 0; p < 4; p++)
                ldm_x4(bfr[0][p][0], bfr[0][p][1], bfr[0][p][2], bfr[0][p][3],
                       sst + A_BYTES + SWZ(bRow + (uint32_t)(p*16*128) + bKoff));
        }

#pragma unroll
        for (int q = 0; q < 8; q++) {
            const int cur = q & 1, nxt = cur ^ 1;
            if (q < 7) {
                const uint32_t hb = sst + (uint32_t)(((q+1) >> 2) * HALF_BYTES);
                const uint32_t kb = (uint32_t)(((q+1) & 3) * 32);
#pragma unroll
                for (int i = 0; i < 4; i++)
                    ldm_x4(afr[nxt][i][0], afr[nxt][i][1],
                           afr[nxt][i][2], afr[nxt][i][3],
                           hb + SWZ(aRow + (uint32_t)(i*16*128) + kb + aKoff));
#pragma unroll
                for (int p = 0; p < 4; p++)
                    ldm_x4(bfr[nxt][p][0], bfr[nxt][p][1],
                           bfr[nxt][p][2], bfr[nxt][p][3],
                           hb + A_BYTES + SWZ(bRow + (uint32_t)(p*16*128) + kb + bKoff));
            }
#pragma unroll
            for (int i = 0; i < 4; i++)
#pragma unroll
                for (int j = 0; j < 8; j++)
                    mma_m16n8k8(acc[i][j], afr[cur][i],
                                bfr[cur][j >> 1][(j & 1)*2],
                                bfr[cur][j >> 1][(j & 1)*2 + 1]);
        }

        MB_ARRIVE(mb + 8*(NSTAGES + cs));   // release mega-stage
    }

    const int rowg = by*BM + wm*64 + (lid >> 2);
    const int colg = bx*BN + wn*64 + (lid & 3)*2;
#pragma unroll
    for (int j = 0; j < 8; j++) {
        const int c = colg + j*8;
        float2 bv = make_float2(0.f, 0.f);
        if (HB) bv = *(const float2*)(bias + c);
#pragma unroll
        for (int i = 0; i < 4; i++) {
            const int r = rowg + i*16;
            float2 v0, v1;
            v0.x = acc[i][j][0]*alpha + bv.x;
            v0.y = acc[i][j][1]*alpha + bv.y;
            v1.x = acc[i][j][2]*alpha + bv.x;
            v1.y = acc[i][j][3]*alpha + bv.y;
            if (ROUND) {
                v0.x = tf32r(v0.x); v0.y = tf32r(v0.y);
                v1.x = tf32r(v1.x); v1.y = tf32r(v1.y);
            }
            *(float2*)(Cb + (size_t)r*ldc + c)     = v0;
            *(float2*)(Cb + (size_t)(r+8)*ldc + c) = v1;
        }
    }
}

// ---------------------------------------------------------------- round x
// g_X = tf32_round(x), vectorized. 16.7M elems / (256 thr * 4) = 16384 blocks.
__global__ void __launch_bounds__(256) round_x(
    const float4* __restrict__ in, float4* __restrict__ out)
{
    const size_t i = (size_t)blockIdx.x * 256 + threadIdx.x;
    float4 v = in[i];
    v.x = tf32r(v.x); v.y = tf32r(v.y);
    v.z = tf32r(v.z); v.w = tf32r(v.w);
    out[i] = v;
}

// ---------------------------------------------------------------- transpose
__global__ void __launch_bounds__(256) transpose_g(
    const float* __restrict__ in, float* __restrict__ out,
    int ldin, int ldout, long sIn, long sOut)
{
    __shared__ float t[32][33];
    const int b = blockIdx.z;
    in  += (size_t)b * sIn;
    out += (size_t)b * sOut;
    const int x = blockIdx.x * 32;
    const int y = blockIdx.y * 32;
#pragma unroll
    for (int j = threadIdx.y; j < 32; j += 8)
        t[j][threadIdx.x] = tf32r(in[(size_t)(y + j)*ldin + x + threadIdx.x]);
    __syncthreads();
#pragma unroll
    for (int j = threadIdx.y; j < 32; j += 8)
        out[(size_t)(x + j)*ldout + y + threadIdx.x] = t[threadIdx.x][j];
}

// ---------------------------------------------------------------- softmax
// Single-pass register-resident causal softmax (8 elems/thread), __expf.
__global__ __launch_bounds__(256)
void softmax_causal(float* __restrict__ S, int T)
{
    const int i = blockIdx.x;
    const int b = blockIdx.y;
    float* row = S + ((size_t)b*T + i)*T;
    const int L = i + 1;
    const int tid = threadIdx.x;

    __shared__ float red[8];
    __shared__ float bval;

    float v[8];
    float m = -1e30f;
#pragma unroll
    for (int k = 0; k < 8; k++) {
        const int j = tid + k*256;
        v[k] = (j < L) ? row[j] : -1e30f;
        m = fmaxf(m, v[k]);
    }
#pragma unroll
    for (int o = 16; o; o >>= 1) m = fmaxf(m, __shfl_xor_sync(0xffffffffu, m, o));
    if ((tid & 31) == 0) red[tid >> 5] = m;
    __syncthreads();
    if (tid == 0) {
        float mm = red[0];
#pragma unroll
        for (int w = 1; w < 8; w++) mm = fmaxf(mm, red[w]);
        bval = mm;
    }
    __syncthreads();
    m = bval;
    __syncthreads();

    float s = 0.0f;
#pragma unroll
    for (int k = 0; k < 8; k++) {
        const int j = tid + k*256;
        v[k] = (j < L) ? __expf(v[k] - m) : 0.0f;
        s += v[k];
    }
#pragma unroll
    for (int o = 16; o; o >>= 1) s += __shfl_xor_sync(0xffffffffu, s, o);
    if ((tid & 31) == 0) red[tid >> 5] = s;
    __syncthreads();
    if (tid == 0) {
        float ss = 0.0f;
#pragma unroll
        for (int w = 0; w < 8; w++) ss += red[w];
        bval = ss;
    }
    __syncthreads();
    const float inv = 1.0f / bval;

    const int end = ((i >> 8) + 1) << 8;
#pragma unroll
    for (int k = 0; k < 8; k++) {
        const int j = tid + k*256;
        if (j < L)        row[j] = tf32r(v[k] * inv);
        else if (j < end) row[j] = 0.0f;
    }
}

// ---------------------------------------------------------------- launch
extern "C" void kernel_launch(void* const* d_in, const int* in_sizes, int n_in,
                              void* d_out, int out_size)
{
    (void)in_sizes; (void)n_in; (void)out_size;
    const float* x      = (const float*)d_in[0];
    const float* W_kqv  = (const float*)d_in[1];
    const float* b_kqv  = (const float*)d_in[2];
    const float* W_proj = (const float*)d_in[3];
    const float* b_proj = (const float*)d_in[4];
    float* out = (float*)d_out;

    float *X, *kqv, *S, *O, *Wt, *WtP, *Vt;
    cudaGetSymbolAddress((void**)&X,   g_X);
    cudaGetSymbolAddress((void**)&kqv, g_kqv);
    cudaGetSymbolAddress((void**)&S,   g_S);
    cudaGetSymbolAddress((void**)&O,   g_O);
    cudaGetSymbolAddress((void**)&Wt,  g_Wt);
    cudaGetSymbolAddress((void**)&WtP, g_WtP);
    cudaGetSymbolAddress((void**)&Vt,  g_Vt);

    const int B = BATCH, T = SEQ, C = CDIM;
    const float scale = 1.0f / sqrtf((float)T);
    const long sBT3C = (long)T*3*C;

    cudaFuncSetAttribute(gemm_tc<false,false,true,true>,
        cudaFuncAttributeMaxDynamicSharedMemorySize, SMEM_DYN);
    cudaFuncSetAttribute(gemm_tc<true,false,false,false>,
        cudaFuncAttributeMaxDynamicSharedMemorySize, SMEM_DYN);
    cudaFuncSetAttribute(gemm_tc<false,true,false,true>,
        cudaFuncAttributeMaxDynamicSharedMemorySize, SMEM_DYN);
    cudaFuncSetAttribute(gemm_tc<false,false,true,false>,
        cudaFuncAttributeMaxDynamicSharedMemorySize, SMEM_DYN);

    // 1) X = tf32_round(x)
    round_x<<<(B*T*C)/(256*4), 256>>>((const float4*)x, (float4*)X);

    // 2) Wt = W_kqv^T (tf32-rounded)
    transpose_g<<<dim3(3*C/32, C/32, 1), dim3(32,8)>>>(W_kqv, Wt, 3*C, C, 0, 0);

    // 3) WtP = W_proj^T
    transpose_g<<<dim3(C/32, C/32, 1), dim3(32,8)>>>(W_proj, WtP, C, C, 0, 0);

    // 4) kqv = X @ W_kqv + b_kqv (all inputs pre-rounded -> no mainloop CVT)
    gemm_tc<false,false,true,true><<<dim3(3*C/BN, (B*T)/BM, 1), 256, SMEM_DYN>>>(
        X, Wt, kqv, b_kqv, C, C, C, 3*C, 0, 0, 0, 1.0f);

    // 5) Vt[b][c][t] = kqv[b*T+t][2C+c]
    transpose_g<<<dim3(C/32, T/32, B), dim3(32,8)>>>(
        kqv + 2*C, Vt, 3*C, T, sBT3C, (long)C*T);

    // 6) S = Q @ K^T * scale (causal block-skip, rows reversed)  <-- profiled
    gemm_tc<true,false,false,false><<<dim3(T/BN, T/BM, B), 256, SMEM_DYN>>>(
        kqv + C, kqv, S, nullptr, C, 3*C, 3*C, T,
        sBT3C, sBT3C, (long)T*T, scale);

    // 7) causal softmax (single-pass, __expf, zeros to 256-block ends)
    softmax_causal<<<dim3(T, B, 1), 256>>>(S, T);

    // 8) O = P @ V (causal k-limit, heavy rows first)
    gemm_tc<false,true,false,true><<<dim3(C/BN, T/BM, B), 256, SMEM_DYN>>>(
        S, Vt, O, nullptr, T, T, T, C,
        (long)T*T, (long)C*T, (long)T*C, 1.0f);

    // 9) out = O @ W_proj + b_proj
    gemm_tc<false,false,true,false><<<dim3(C/BN, (B*T)/BM, 1), 256, SMEM_DYN>>>(
        O, WtP, out, b_proj, C, C, C, C, 0, 0, 0, 1.0f);
}

// round 14
// speedup vs baseline: 1.8297x; 1.4444x over previous
#include <cuda_runtime.h>
#include <cuda_fp16.h>
#include <cstdint>
#include <math.h>

// ---------------------------------------------------------------- constants
#define BATCH 8
#define SEQ   2048
#define CDIM  1024

#define BM 256
#define BN 128
#define NSTAGES 2
#define A_BYTES 32768               // 256 rows x 128B (64 fp16)
#define B_BYTES 16384               // 128 rows x 128B
#define HALF_BYTES (A_BYTES + B_BYTES)      // 48KB: one 64-K sub-tile
#define STAGE_BYTES (2*HALF_BYTES)          // 96KB: one 128-K mega-stage
#define SMEM_DYN (NSTAGES*STAGE_BYTES + 1024)

#define SWZ(x) ((x) ^ (((x)>>3)&0x70))

// ---------------------------------------------------------------- scratch
__device__ __half g_X  [(size_t)BATCH*SEQ*CDIM];    // fp16 x
__device__ __half g_kqv[(size_t)BATCH*SEQ*3*CDIM];  // [B*T, 3C] fp16
__device__ float  g_S  [(size_t)BATCH*SEQ*SEQ];     // [B, T, T] fp32 scores
__device__ __half g_P  [(size_t)BATCH*SEQ*SEQ];     // [B, T, T] fp16 probs
__device__ __half g_O  [(size_t)BATCH*SEQ*CDIM];    // [B*T, C] fp16
__device__ __half g_Wt [(size_t)3*CDIM*CDIM];       // W_kqv^T  [3C, C] fp16
__device__ __half g_WtP[(size_t)CDIM*CDIM];         // W_proj^T [C, C] fp16
__device__ __half g_Vt [(size_t)BATCH*CDIM*SEQ];    // V^T per batch [C, T] fp16

// ---------------------------------------------------------------- ptx utils
__device__ __forceinline__ uint32_t smem_u32(const void* p){
    uint32_t a;
    asm("{ .reg .u64 t; cvta.to.shared.u64 t, %1; cvt.u32.u64 %0, t; }"
        : "=r"(a) : "l"(p));
    return a;
}
__device__ __forceinline__ void cp16(uint32_t dst, const void* src){
    asm volatile("cp.async.cg.shared.global [%0], [%1], 16;" :: "r"(dst), "l"(src));
}
#define MB_INIT(a, c) \
    asm volatile("mbarrier.init.shared.b64 [%0], %1;" :: "r"(a), "r"(c) : "memory")
#define MB_ARRIVE(a) \
    asm volatile("mbarrier.arrive.shared.b64 _, [%0];" :: "r"(a) : "memory")
#define CP_MBAR_NOINC(a) \
    asm volatile("cp.async.mbarrier.arrive.noinc.shared.b64 [%0];" :: "r"(a) : "memory")

#define MB_WAIT_PARITY(a, ph) do { \
    uint32_t _m=(uint32_t)(a), _p=(uint32_t)(ph), _d; \
    asm volatile("{\n\t.reg .pred p;\n\t" \
        "mbarrier.try_wait.parity.acquire.cta.shared::cta.b64 p, [%1], %2;\n\t" \
        "selp.b32 %0, 1, 0, p;\n\t}" : "=r"(_d) : "r"(_m), "r"(_p) : "memory"); \
    if (!_d) { \
        asm volatile("{\n\t.reg .pred P1;\n\tWL_%=:\n\t" \
            "mbarrier.try_wait.parity.acquire.cta.shared::cta.b64 P1, [%0], %1, 0x989680;\n\t" \
            "@P1 bra.uni WD_%=;\n\tbra.uni WL_%=;\n\tWD_%=:\n\t}" \
            :: "r"(_m), "r"(_p) : "memory"); \
    } } while(0)

__device__ __forceinline__ void ldm_x4(uint32_t& r0, uint32_t& r1,
                                       uint32_t& r2, uint32_t& r3, uint32_t a){
    asm volatile("ldmatrix.sync.aligned.m8n8.x4.shared.b16 {%0,%1,%2,%3}, [%4];"
        : "=r"(r0), "=r"(r1), "=r"(r2), "=r"(r3) : "r"(a));
}

__device__ __forceinline__ uint32_t pack_h2(float lo, float hi){
    __half2 h = __floats2half2_rn(lo, hi);
    uint32_t u;
    memcpy(&u, &h, 4);
    return u;
}

// fp16 MMA: D(fp32) = A(fp16) * B(fp16) + C(fp32), m16n8k16
__device__ __forceinline__ void mma_f16(float* c, const uint32_t* a,
                                        uint32_t b0, uint32_t b1){
    asm volatile(
        "mma.sync.aligned.m16n8k16.row.col.f32.f16.f16.f32 "
        "{%0,%1,%2,%3}, {%4,%5,%6,%7}, {%8,%9}, {%0,%1,%2,%3};"
        : "+f"(c[0]), "+f"(c[1]), "+f"(c[2]), "+f"(c[3])
        : "r"(a[0]), "r"(a[1]), "r"(a[2]), "r"(a[3]), "r"(b0), "r"(b1));
}

// ---------------------------------------------------------------- tile loader
// A: 256 rows x 64 fp16 (128B rows, SW128), 8 cp16/thread; B: 128 rows, 4/thread.
__device__ __forceinline__ void load_half_tile(uint32_t sA, uint32_t sB,
    const __half* __restrict__ Ab, const __half* __restrict__ Bb,
    int lda, int ldb, int k0, int tid)
{
#pragma unroll
    for (int i = 0; i < 8; i++) {
        int idx = tid + i*256;
        int row = idx >> 3;
        int ck  = (idx & 7) << 3;              // fp16 elems within row
        uint32_t so = SWZ((uint32_t)(row*128 + ck*2));
        cp16(sA + so, Ab + (size_t)row*lda + k0 + ck);
    }
#pragma unroll
    for (int i = 0; i < 4; i++) {
        int idx = tid + i*256;
        int row = idx >> 3;
        int ck  = (idx & 7) << 3;
        uint32_t so = SWZ((uint32_t)(row*128 + ck*2));
        cp16(sB + so, Bb + (size_t)row*ldb + k0 + ck);
    }
}

// ---------------------------------------------------------------- mma GEMM
// C[bz][m][n] = alpha * sum_k A[bz][m][k]*B[bz][n][k] (+bias[n]). NT, fp16 in,
// fp32 accum, OUTT out. 256x128 CTA tile, 8 warps (4x2) of 64x64.
// mbarrier pipeline, 128-K mega-stages.
template<bool CSKIP, bool CK, bool HB, typename OUTT>
__global__ void __launch_bounds__(256) gemm_tc(
    const __half* __restrict__ A, const __half* __restrict__ B,
    OUTT* __restrict__ C, const float* __restrict__ bias,
    int K, int lda, int ldb, int ldc, long sA, long sB, long sC, float alpha)
{
    const int bx = blockIdx.x, bz = blockIdx.z;
    const int by = (CSKIP || CK) ? ((int)gridDim.y - 1 - (int)blockIdx.y)
                                 : (int)blockIdx.y;
    if (CSKIP && bx > 2*by + 1) return;

    extern __shared__ char smem[];
    __shared__ uint64_t mbars[2*NSTAGES];   // full0,full1,empty0,empty1
    const uint32_t tb = (smem_u32(smem) + 1023) & ~1023u;
    const uint32_t mb = smem_u32(mbars);
    const int tid = threadIdx.x, wid = tid >> 5, lid = tid & 31;
    const int wm = wid >> 1;       // 4 m-blocks of 64
    const int wn = wid & 1;        // 2 n-blocks of 64

    const __half* Ab = A + (size_t)bz*sA + (size_t)by*BM*lda;
    const __half* Bb = B + (size_t)bz*sB + (size_t)bx*BN*ldb;
    OUTT* Cb = C + (size_t)bz*sC;
    const int kEnd = CK ? min(K, (by + 1)*BM) : K;
    const int iters = kEnd >> 7;   // 128-K mega-iters, >= 2 always

    if (tid == 0) {
#pragma unroll
        for (int s = 0; s < NSTAGES; s++) {
            MB_INIT(mb + 8*s, 256);                 // full[s]
            MB_INIT(mb + 8*(NSTAGES + s), 256);     // empty[s]
        }
    }
    __syncthreads();

    float acc[4][8][4];
#pragma unroll
    for (int i = 0; i < 4; i++)
#pragma unroll
        for (int j = 0; j < 8; j++)
#pragma unroll
            for (int r = 0; r < 4; r++) acc[i][j][r] = 0.0f;

    // ldmatrix lane addressing (bytes in tile): rows (L&15), k-halves (L>>4)
    const uint32_t aRow  = (uint32_t)((wm*64 + (lid & 15)) * 128);
    const uint32_t bRow  = (uint32_t)((wn*64 + (lid & 15)) * 128);
    const uint32_t kSel  = (uint32_t)((lid >> 4) * 16);

    // prologue: produce iter 0 into stage 0
    load_half_tile(tb,              tb + A_BYTES,              Ab, Bb, lda, ldb, 0,  tid);
    load_half_tile(tb + HALF_BYTES, tb + HALF_BYTES + A_BYTES, Ab, Bb, lda, ldb, 64, tid);
    CP_MBAR_NOINC(mb);

    uint32_t afr[2][4][4], bfr[2][4][4];

    for (int it = 0; it < iters; ++it) {
        // ---- produce iter it+1 ----
        const int nit = it + 1;
        if (nit < iters) {
            const int ps = nit & 1;
            if (nit >= 2)
                MB_WAIT_PARITY(mb + 8*(NSTAGES + ps), ((nit - 2) >> 1) & 1);
            const uint32_t st = tb + ps*STAGE_BYTES;
            load_half_tile(st,              st + A_BYTES,
                           Ab, Bb, lda, ldb, nit*128,      tid);
            load_half_tile(st + HALF_BYTES, st + HALF_BYTES + A_BYTES,
                           Ab, Bb, lda, ldb, nit*128 + 64, tid);
            CP_MBAR_NOINC(mb + 8*ps);
        }

        // ---- consume iter it ----
        const int cs = it & 1;
        MB_WAIT_PARITY(mb + 8*cs, (it >> 1) & 1);
        const uint32_t sst = tb + cs*STAGE_BYTES;

        // preload chunk q=0 fragments (16-K chunks; 8 per mega-stage)
        {
#pragma unroll
            for (int i = 0; i < 4; i++)
                ldm_x4(afr[0][i][0], afr[0][i][1], afr[0][i][2], afr[0][i][3],
                       sst + SWZ(aRow + (uint32_t)(i*16*128) + kSel));
#pragma unroll
            for (int p = 0; p < 4; p++)
                ldm_x4(bfr[0][p][0], bfr[0][p][1], bfr[0][p][2], bfr[0][p][3],
                       sst + A_BYTES + SWZ(bRow + (uint32_t)(p*16*128) + kSel));
        }

#pragma unroll
        for (int q = 0; q < 8; q++) {
            const int cur = q & 1, nxt = cur ^ 1;
            if (q < 7) {
                const uint32_t hb = sst + (uint32_t)(((q+1) >> 2) * HALF_BYTES);
                const uint32_t kb = (uint32_t)(((q+1) & 3) * 32);   // 16 fp16 = 32B
#pragma unroll
                for (int i = 0; i < 4; i++)
                    ldm_x4(afr[nxt][i][0], afr[nxt][i][1],
                           afr[nxt][i][2], afr[nxt][i][3],
                           hb + SWZ(aRow + (uint32_t)(i*16*128) + kb + kSel));
#pragma unroll
                for (int p = 0; p < 4; p++)
                    ldm_x4(bfr[nxt][p][0], bfr[nxt][p][1],
                           bfr[nxt][p][2], bfr[nxt][p][3],
                           hb + A_BYTES + SWZ(bRow + (uint32_t)(p*16*128) + kb + kSel));
            }
            // bfr[p] = {b0(n=2p), b0(n=2p+1), b1(n=2p), b1(n=2p+1)}
#pragma unroll
            for (int i = 0; i < 4; i++)
#pragma unroll
                for (int j = 0; j < 8; j++)
                    mma_f16(acc[i][j], afr[cur][i],
                            bfr[cur][j >> 1][j & 1],
                            bfr[cur][j >> 1][(j & 1) + 2]);
        }

        MB_ARRIVE(mb + 8*(NSTAGES + cs));   // release mega-stage
    }

    const int rowg = by*BM + wm*64 + (lid >> 2);
    const int colg = bx*BN + wn*64 + (lid & 3)*2;
#pragma unroll
    for (int j = 0; j < 8; j++) {
        const int c = colg + j*8;
        float2 bv = make_float2(0.f, 0.f);
        if (HB) bv = *(const float2*)(bias + c);
#pragma unroll
        for (int i = 0; i < 4; i++) {
            const int r = rowg + i*16;
            float2 v0, v1;
            v0.x = acc[i][j][0]*alpha + bv.x;
            v0.y = acc[i][j][1]*alpha + bv.y;
            v1.x = acc[i][j][2]*alpha + bv.x;
            v1.y = acc[i][j][3]*alpha + bv.y;
            if (sizeof(OUTT) == 2) {
                *(uint32_t*)((__half*)(Cb + (size_t)r*ldc) + c)     = pack_h2(v0.x, v0.y);
                *(uint32_t*)((__half*)(Cb + (size_t)(r+8)*ldc) + c) = pack_h2(v1.x, v1.y);
            } else {
                *(float2*)((float*)(Cb + (size_t)r*ldc) + c)     = v0;
                *(float2*)((float*)(Cb + (size_t)(r+8)*ldc) + c) = v1;
            }
        }
    }
}

// ---------------------------------------------------------------- round x
// g_X = fp16(x). 8 floats/thread -> uint4 (8 halves).
__global__ void __launch_bounds__(256) round_x(
    const float4* __restrict__ in, uint4* __restrict__ out)
{
    const size_t i = (size_t)blockIdx.x * 256 + threadIdx.x;
    float4 a = in[2*i], b = in[2*i + 1];
    uint4 o;
    o.x = pack_h2(a.x, a.y);
    o.y = pack_h2(a.z, a.w);
    o.z = pack_h2(b.x, b.y);
    o.w = pack_h2(b.z, b.w);
    out[i] = o;
}

// ---------------------------------------------------------------- transpose
// out[c][r] = fp16(in[r][c]); TIN = float or __half.
template<typename TIN>
__global__ void __launch_bounds__(256) transpose_g(
    const TIN* __restrict__ in, __half* __restrict__ out,
    int ldin, int ldout, long sIn, long sOut)
{
    __shared__ __half t[32][34];
    const int b = blockIdx.z;
    in  += (size_t)b * sIn;
    out += (size_t)b * sOut;
    const int x = blockIdx.x * 32;
    const int y = blockIdx.y * 32;
#pragma unroll
    for (int j = threadIdx.y; j < 32; j += 8)
        t[j][threadIdx.x] = __float2half_rn((float)in[(size_t)(y + j)*ldin + x + threadIdx.x]);
    __syncthreads();
#pragma unroll
    for (int j = threadIdx.y; j < 32; j += 8)
        out[(size_t)(x + j)*ldout + y + threadIdx.x] = t[threadIdx.x][j];
}

// ---------------------------------------------------------------- softmax
// Reads fp32 S row, writes fp16 P (zero-filled to 256-block end).
__global__ __launch_bounds__(256)
void softmax_causal(const float* __restrict__ S, __half* __restrict__ P, int T)
{
    const int i = blockIdx.x;
    const int b = blockIdx.y;
    const float* row = S + ((size_t)b*T + i)*T;
    __half* prow     = P + ((size_t)b*T + i)*T;
    const int L = i + 1;
    const int tid = threadIdx.x;

    __shared__ float red[8];
    __shared__ float bval;

    float v[8];
    float m = -1e30f;
#pragma unroll
    for (int k = 0; k < 8; k++) {
        const int j = tid + k*256;
        v[k] = (j < L) ? row[j] : -1e30f;
        m = fmaxf(m, v[k]);
    }
#pragma unroll
    for (int o = 16; o; o >>= 1) m = fmaxf(m, __shfl_xor_sync(0xffffffffu, m, o));
    if ((tid & 31) == 0) red[tid >> 5] = m;
    __syncthreads();
    if (tid == 0) {
        float mm = red[0];
#pragma unroll
        for (int w = 1; w < 8; w++) mm = fmaxf(mm, red[w]);
        bval = mm;
    }
    __syncthreads();
    m = bval;
    __syncthreads();

    float s = 0.0f;
#pragma unroll
    for (int k = 0; k < 8; k++) {
        const int j = tid + k*256;
        v[k] = (j < L) ? __expf(v[k] - m) : 0.0f;
        s += v[k];
    }
#pragma unroll
    for (int o = 16; o; o >>= 1) s += __shfl_xor_sync(0xffffffffu, s, o);
    if ((tid & 31) == 0) red[tid >> 5] = s;
    __syncthreads();
    if (tid == 0) {
        float ss = 0.0f;
#pragma unroll
        for (int w = 0; w < 8; w++) ss += red[w];
        bval = ss;
    }
    __syncthreads();
    const float inv = 1.0f / bval;

    const int end = ((i >> 8) + 1) << 8;
#pragma unroll
    for (int k = 0; k < 8; k++) {
        const int j = tid + k*256;
        if (j < L)        prow[j] = __float2half_rn(v[k] * inv);
        else if (j < end) prow[j] = __ushort_as_half(0);
    }
}

// ---------------------------------------------------------------- launch
extern "C" void kernel_launch(void* const* d_in, const int* in_sizes, int n_in,
                              void* d_out, int out_size)
{
    (void)in_sizes; (void)n_in; (void)out_size;
    const float* x      = (const float*)d_in[0];
    const float* W_kqv  = (const float*)d_in[1];
    const float* b_kqv  = (const float*)d_in[2];
    const float* W_proj = (const float*)d_in[3];
    const float* b_proj = (const float*)d_in[4];
    float* out = (float*)d_out;

    __half *X, *kqv, *P, *O, *Wt, *WtP, *Vt;
    float *S;
    cudaGetSymbolAddress((void**)&X,   g_X);
    cudaGetSymbolAddress((void**)&kqv, g_kqv);
    cudaGetSymbolAddress((void**)&S,   g_S);
    cudaGetSymbolAddress((void**)&P,   g_P);
    cudaGetSymbolAddress((void**)&O,   g_O);
    cudaGetSymbolAddress((void**)&Wt,  g_Wt);
    cudaGetSymbolAddress((void**)&WtP, g_WtP);
    cudaGetSymbolAddress((void**)&Vt,  g_Vt);

    const int B = BATCH, T = SEQ, C = CDIM;
    const float scale = 1.0f / sqrtf((float)T);
    const long sBT3C = (long)T*3*C;

    cudaFuncSetAttribute(gemm_tc<false,false,true,__half>,
        cudaFuncAttributeMaxDynamicSharedMemorySize, SMEM_DYN);
    cudaFuncSetAttribute(gemm_tc<true,false,false,float>,
        cudaFuncAttributeMaxDynamicSharedMemorySize, SMEM_DYN);
    cudaFuncSetAttribute(gemm_tc<false,true,false,__half>,
        cudaFuncAttributeMaxDynamicSharedMemorySize, SMEM_DYN);
    cudaFuncSetAttribute(gemm_tc<false,false,true,float>,
        cudaFuncAttributeMaxDynamicSharedMemorySize, SMEM_DYN);

    // 1) X = fp16(x)
    round_x<<<(B*T*C)/(256*8), 256>>>((const float4*)x, (uint4*)X);

    // 2) Wt = fp16(W_kqv^T)
    transpose_g<float><<<dim3(3*C/32, C/32, 1), dim3(32,8)>>>(W_kqv, Wt, 3*C, C, 0, 0);

    // 3) WtP = fp16(W_proj^T)
    transpose_g<float><<<dim3(C/32, C/32, 1), dim3(32,8)>>>(W_proj, WtP, C, C, 0, 0);

    // 4) kqv = X @ W_kqv + b_kqv   (fp16 out)
    gemm_tc<false,false,true,__half><<<dim3(3*C/BN, (B*T)/BM, 1), 256, SMEM_DYN>>>(
        X, Wt, kqv, b_kqv, C, C, C, 3*C, 0, 0, 0, 1.0f);

    // 5) Vt[b][c][t] = kqv[b*T+t][2C+c]  (fp16 -> fp16)
    transpose_g<__half><<<dim3(C/32, T/32, B), dim3(32,8)>>>(
        kqv + 2*C, Vt, 3*C, T, sBT3C, (long)C*T);

    // 6) S = Q @ K^T * scale (fp32 out, causal block-skip)   <-- profiled
    gemm_tc<true,false,false,float><<<dim3(T/BN, T/BM, B), 256, SMEM_DYN>>>(
        kqv + C, kqv, S, nullptr, C, 3*C, 3*C, T,
        sBT3C, sBT3C, (long)T*T, scale);

    // 7) causal softmax: P = fp16(softmax(S)), zeros to 256-block ends
    softmax_causal<<<dim3(T, B, 1), 256>>>(S, P, T);

    // 8) O = P @ V (fp16 out, causal k-limit, heavy rows first)
    gemm_tc<false,true,false,__half><<<dim3(C/BN, T/BM, B), 256, SMEM_DYN>>>(
        P, Vt, O, nullptr, T, T, T, C,
        (long)T*T, (long)C*T, (long)T*C, 1.0f);

    // 9) out = O @ W_proj + b_proj (fp32 out)
    gemm_tc<false,false,true,float><<<dim3(C/BN, (B*T)/BM, 1), 256, SMEM_DYN>>>(
        O, WtP, out, b_proj, C, C, C, C, 0, 0, 0, 1.0f);
}

// round 15
// speedup vs baseline: 1.8318x; 1.0012x over previous
#include <cuda_runtime.h>
#include <cuda_fp16.h>
#include <cstdint>
#include <math.h>

// ---------------------------------------------------------------- constants
#define BATCH 8
#define SEQ   2048
#define CDIM  1024

#define BM 256
#define BN 128
#define NSTAGES 2
#define A_BYTES 32768               // 256 rows x 128B (64 fp16)
#define B_BYTES 16384               // 128 rows x 128B
#define HALF_BYTES (A_BYTES + B_BYTES)      // 48KB: one 64-K sub-tile
#define STAGE_BYTES (2*HALF_BYTES)          // 96KB: one 128-K mega-stage
#define SMEM_DYN (NSTAGES*STAGE_BYTES + 1024)

#define SWZ(x) ((x) ^ (((x)>>3)&0x70))

// ---------------------------------------------------------------- scratch
__device__ __half g_X  [(size_t)BATCH*SEQ*CDIM];    // fp16 x
__device__ __half g_kqv[(size_t)BATCH*SEQ*3*CDIM];  // [B*T, 3C] fp16
__device__ float  g_S  [(size_t)BATCH*SEQ*SEQ];     // [B, T, T] fp32 scores
__device__ __half g_P  [(size_t)BATCH*SEQ*SEQ];     // [B, T, T] fp16 probs
__device__ __half g_O  [(size_t)BATCH*SEQ*CDIM];    // [B*T, C] fp16
__device__ __half g_Wt [(size_t)3*CDIM*CDIM];       // W_kqv^T  [3C, C] fp16
__device__ __half g_WtP[(size_t)CDIM*CDIM];         // W_proj^T [C, C] fp16
__device__ __half g_Vt [(size_t)BATCH*CDIM*SEQ];    // V^T per batch [C, T] fp16

// ---------------------------------------------------------------- ptx utils
__device__ __forceinline__ uint32_t smem_u32(const void* p){
    uint32_t a;
    asm("{ .reg .u64 t; cvta.to.shared.u64 t, %1; cvt.u32.u64 %0, t; }"
        : "=r"(a) : "l"(p));
    return a;
}
__device__ __forceinline__ void cp16(uint32_t dst, const void* src){
    asm volatile("cp.async.cg.shared.global [%0], [%1], 16;" :: "r"(dst), "l"(src));
}
#define MB_INIT(a, c) \
    asm volatile("mbarrier.init.shared.b64 [%0], %1;" :: "r"(a), "r"(c) : "memory")
#define MB_ARRIVE(a) \
    asm volatile("mbarrier.arrive.shared.b64 _, [%0];" :: "r"(a) : "memory")
#define CP_MBAR_NOINC(a) \
    asm volatile("cp.async.mbarrier.arrive.noinc.shared.b64 [%0];" :: "r"(a) : "memory")

#define MB_WAIT_PARITY(a, ph) do { \
    uint32_t _m=(uint32_t)(a), _p=(uint32_t)(ph), _d; \
    asm volatile("{\n\t.reg .pred p;\n\t" \
        "mbarrier.try_wait.parity.acquire.cta.shared::cta.b64 p, [%1], %2;\n\t" \
        "selp.b32 %0, 1, 0, p;\n\t}" : "=r"(_d) : "r"(_m), "r"(_p) : "memory"); \
    if (!_d) { \
        asm volatile("{\n\t.reg .pred P1;\n\tWL_%=:\n\t" \
            "mbarrier.try_wait.parity.acquire.cta.shared::cta.b64 P1, [%0], %1, 0x989680;\n\t" \
            "@P1 bra.uni WD_%=;\n\tbra.uni WL_%=;\n\tWD_%=:\n\t}" \
            :: "r"(_m), "r"(_p) : "memory"); \
    } } while(0)

__device__ __forceinline__ void ldm_x4(uint32_t& r0, uint32_t& r1,
                                       uint32_t& r2, uint32_t& r3, uint32_t a){
    asm volatile("ldmatrix.sync.aligned.m8n8.x4.shared.b16 {%0,%1,%2,%3}, [%4];"
        : "=r"(r0), "=r"(r1), "=r"(r2), "=r"(r3) : "r"(a));
}

__device__ __forceinline__ uint32_t pack_h2(float lo, float hi){
    __half2 h = __floats2half2_rn(lo, hi);
    uint32_t u;
    memcpy(&u, &h, 4);
    return u;
}

// fp16 MMA: D(fp32) = A(fp16) * B(fp16) + C(fp32), m16n8k16
__device__ __forceinline__ void mma_f16(float* c, const uint32_t* a,
                                        uint32_t b0, uint32_t b1){
    asm volatile(
        "mma.sync.aligned.m16n8k16.row.col.f32.f16.f16.f32 "
        "{%0,%1,%2,%3}, {%4,%5,%6,%7}, {%8,%9}, {%0,%1,%2,%3};"
        : "+f"(c[0]), "+f"(c[1]), "+f"(c[2]), "+f"(c[3])
        : "r"(a[0]), "r"(a[1]), "r"(a[2]), "r"(a[3]), "r"(b0), "r"(b1));
}

// ---------------------------------------------------------------- tile loader
// A: 256 rows x 64 fp16 (128B rows, SW128), 8 cp16/thread; B: 128 rows, 4/thread.
__device__ __forceinline__ void load_half_tile(uint32_t sA, uint32_t sB,
    const __half* __restrict__ Ab, const __half* __restrict__ Bb,
    int lda, int ldb, int k0, int tid)
{
#pragma unroll
    for (int i = 0; i < 8; i++) {
        int idx = tid + i*256;
        int row = idx >> 3;
        int ck  = (idx & 7) << 3;              // fp16 elems within row
        uint32_t so = SWZ((uint32_t)(row*128 + ck*2));
        cp16(sA + so, Ab + (size_t)row*lda + k0 + ck);
    }
#pragma unroll
    for (int i = 0; i < 4; i++) {
        int idx = tid + i*256;
        int row = idx >> 3;
        int ck  = (idx & 7) << 3;
        uint32_t so = SWZ((uint32_t)(row*128 + ck*2));
        cp16(sB + so, Bb + (size_t)row*ldb + k0 + ck);
    }
}

// ---------------------------------------------------------------- mma GEMM
// C[bz][m][n] = alpha * sum_k A[bz][m][k]*B[bz][n][k] (+bias[n]). NT, fp16 in,
// fp32 accum, OUTT out. 256x128 CTA tile, 8 warps (4x2) of 64x64.
// mbarrier pipeline, 128-K mega-stages. Consumer-first ordering:
// full-wait -> preload q0 -> produce next (off critical path) -> chunks;
// empty-arrive fires right after the stage's LAST ldmatrix (q==6), since
// MMAs read registers, not smem.
template<bool CSKIP, bool CK, bool HB, typename OUTT>
__global__ void __launch_bounds__(256) gemm_tc(
    const __half* __restrict__ A, const __half* __restrict__ B,
    OUTT* __restrict__ C, const float* __restrict__ bias,
    int K, int lda, int ldb, int ldc, long sA, long sB, long sC, float alpha)
{
    const int bx = blockIdx.x, bz = blockIdx.z;
    const int by = (CSKIP || CK) ? ((int)gridDim.y - 1 - (int)blockIdx.y)
                                 : (int)blockIdx.y;
    if (CSKIP && bx > 2*by + 1) return;

    extern __shared__ char smem[];
    __shared__ uint64_t mbars[2*NSTAGES];   // full0,full1,empty0,empty1
    const uint32_t tb = (smem_u32(smem) + 1023) & ~1023u;
    const uint32_t mb = smem_u32(mbars);
    const int tid = threadIdx.x, wid = tid >> 5, lid = tid & 31;
    const int wm = wid >> 1;       // 4 m-blocks of 64
    const int wn = wid & 1;        // 2 n-blocks of 64

    const __half* Ab = A + (size_t)bz*sA + (size_t)by*BM*lda;
    const __half* Bb = B + (size_t)bz*sB + (size_t)bx*BN*ldb;
    OUTT* Cb = C + (size_t)bz*sC;
    const int kEnd = CK ? min(K, (by + 1)*BM) : K;
    const int iters = kEnd >> 7;   // 128-K mega-iters, >= 2 always

    if (tid == 0) {
#pragma unroll
        for (int s = 0; s < NSTAGES; s++) {
            MB_INIT(mb + 8*s, 256);                 // full[s]
            MB_INIT(mb + 8*(NSTAGES + s), 256);     // empty[s]
        }
    }
    __syncthreads();

    float acc[4][8][4];
#pragma unroll
    for (int i = 0; i < 4; i++)
#pragma unroll
        for (int j = 0; j < 8; j++)
#pragma unroll
            for (int r = 0; r < 4; r++) acc[i][j][r] = 0.0f;

    // ldmatrix lane addressing (bytes in tile): rows (L&15), k-halves (L>>4)
    const uint32_t aRow  = (uint32_t)((wm*64 + (lid & 15)) * 128);
    const uint32_t bRow  = (uint32_t)((wn*64 + (lid & 15)) * 128);
    const uint32_t kSel  = (uint32_t)((lid >> 4) * 16);

    // prologue: produce iter 0 into stage 0
    load_half_tile(tb,              tb + A_BYTES,              Ab, Bb, lda, ldb, 0,  tid);
    load_half_tile(tb + HALF_BYTES, tb + HALF_BYTES + A_BYTES, Ab, Bb, lda, ldb, 64, tid);
    CP_MBAR_NOINC(mb);

    uint32_t afr[2][4][4], bfr[2][4][4];

    for (int it = 0; it < iters; ++it) {
        // ---- consume gate first: stage it&1 ready? ----
        const int cs = it & 1;
        MB_WAIT_PARITY(mb + 8*cs, (it >> 1) & 1);
        const uint32_t sst = tb + cs*STAGE_BYTES;

        // preload chunk q=0 fragments immediately (MMAs can start)
        {
#pragma unroll
            for (int i = 0; i < 4; i++)
                ldm_x4(afr[0][i][0], afr[0][i][1], afr[0][i][2], afr[0][i][3],
                       sst + SWZ(aRow + (uint32_t)(i*16*128) + kSel));
#pragma unroll
            for (int p = 0; p < 4; p++)
                ldm_x4(bfr[0][p][0], bfr[0][p][1], bfr[0][p][2], bfr[0][p][3],
                       sst + A_BYTES + SWZ(bRow + (uint32_t)(p*16*128) + kSel));
        }

        // ---- produce iter it+1 (off the critical path; cp.async is fire-and-forget)
        const int nit = it + 1;
        if (nit < iters) {
            const int ps = nit & 1;
            if (nit >= 2)
                MB_WAIT_PARITY(mb + 8*(NSTAGES + ps), ((nit - 2) >> 1) & 1);
            const uint32_t st = tb + ps*STAGE_BYTES;
            load_half_tile(st,              st + A_BYTES,
                           Ab, Bb, lda, ldb, nit*128,      tid);
            load_half_tile(st + HALF_BYTES, st + HALF_BYTES + A_BYTES,
                           Ab, Bb, lda, ldb, nit*128 + 64, tid);
            CP_MBAR_NOINC(mb + 8*ps);
        }

        // ---- compute 8 chunks of K=16 ----
#pragma unroll
        for (int q = 0; q < 8; q++) {
            const int cur = q & 1, nxt = cur ^ 1;
            if (q < 7) {
                const uint32_t hb = sst + (uint32_t)(((q+1) >> 2) * HALF_BYTES);
                const uint32_t kb = (uint32_t)(((q+1) & 3) * 32);   // 16 fp16 = 32B
#pragma unroll
                for (int i = 0; i < 4; i++)
                    ldm_x4(afr[nxt][i][0], afr[nxt][i][1],
                           afr[nxt][i][2], afr[nxt][i][3],
                           hb + SWZ(aRow + (uint32_t)(i*16*128) + kb + kSel));
#pragma unroll
                for (int p = 0; p < 4; p++)
                    ldm_x4(bfr[nxt][p][0], bfr[nxt][p][1],
                           bfr[nxt][p][2], bfr[nxt][p][3],
                           hb + A_BYTES + SWZ(bRow + (uint32_t)(p*16*128) + kb + kSel));
            }
            // after q==6's preload, this thread's LAST smem read of stage cs
            // is done (q=7 frags are in registers) -> release the stage early.
            if (q == 6) MB_ARRIVE(mb + 8*(NSTAGES + cs));

            // bfr[p] = {b0(n=2p), b0(n=2p+1), b1(n=2p), b1(n=2p+1)}
#pragma unroll
            for (int i = 0; i < 4; i++)
#pragma unroll
                for (int j = 0; j < 8; j++)
                    mma_f16(acc[i][j], afr[cur][i],
                            bfr[cur][j >> 1][j & 1],
                            bfr[cur][j >> 1][(j & 1) + 2]);
        }
    }

    const int rowg = by*BM + wm*64 + (lid >> 2);
    const int colg = bx*BN + wn*64 + (lid & 3)*2;
#pragma unroll
    for (int j = 0; j < 8; j++) {
        const int c = colg + j*8;
        float2 bv = make_float2(0.f, 0.f);
        if (HB) bv = *(const float2*)(bias + c);
#pragma unroll
        for (int i = 0; i < 4; i++) {
            const int r = rowg + i*16;
            float2 v0, v1;
            v0.x = acc[i][j][0]*alpha + bv.x;
            v0.y = acc[i][j][1]*alpha + bv.y;
            v1.x = acc[i][j][2]*alpha + bv.x;
            v1.y = acc[i][j][3]*alpha + bv.y;
            if (sizeof(OUTT) == 2) {
                *(uint32_t*)((__half*)(Cb + (size_t)r*ldc) + c)     = pack_h2(v0.x, v0.y);
                *(uint32_t*)((__half*)(Cb + (size_t)(r+8)*ldc) + c) = pack_h2(v1.x, v1.y);
            } else {
                *(float2*)((float*)(Cb + (size_t)r*ldc) + c)     = v0;
                *(float2*)((float*)(Cb + (size_t)(r+8)*ldc) + c) = v1;
            }
        }
    }
}

// ---------------------------------------------------------------- round x
// g_X = fp16(x). 8 floats/thread -> uint4 (8 halves).
__global__ void __launch_bounds__(256) round_x(
    const float4* __restrict__ in, uint4* __restrict__ out)
{
    const size_t i = (size_t)blockIdx.x * 256 + threadIdx.x;
    float4 a = in[2*i], b = in[2*i + 1];
    uint4 o;
    o.x = pack_h2(a.x, a.y);
    o.y = pack_h2(a.z, a.w);
    o.z = pack_h2(b.x, b.y);
    o.w = pack_h2(b.z, b.w);
    out[i] = o;
}

// ---------------------------------------------------------------- transpose
// out[c][r] = fp16(in[r][c]); TIN = float or __half.
template<typename TIN>
__global__ void __launch_bounds__(256) transpose_g(
    const TIN* __restrict__ in, __half* __restrict__ out,
    int ldin, int ldout, long sIn, long sOut)
{
    __shared__ __half t[32][34];
    const int b = blockIdx.z;
    in  += (size_t)b * sIn;
    out += (size_t)b * sOut;
    const int x = blockIdx.x * 32;
    const int y = blockIdx.y * 32;
#pragma unroll
    for (int j = threadIdx.y; j < 32; j += 8)
        t[j][threadIdx.x] = __float2half_rn((float)in[(size_t)(y + j)*ldin + x + threadIdx.x]);
    __syncthreads();
#pragma unroll
    for (int j = threadIdx.y; j < 32; j += 8)
        out[(size_t)(x + j)*ldout + y + threadIdx.x] = t[threadIdx.x][j];
}

// ---------------------------------------------------------------- softmax
// Reads fp32 S row, writes fp16 P (zero-filled to 256-block end).
__global__ __launch_bounds__(256)
void softmax_causal(const float* __restrict__ S, __half* __restrict__ P, int T)
{
    const int i = blockIdx.x;
    const int b = blockIdx.y;
    const float* row = S + ((size_t)b*T + i)*T;
    __half* prow     = P + ((size_t)b*T + i)*T;
    const int L = i + 1;
    const int tid = threadIdx.x;

    __shared__ float red[8];
    __shared__ float bval;

    float v[8];
    float m = -1e30f;
#pragma unroll
    for (int k = 0; k < 8; k++) {
        const int j = tid + k*256;
        v[k] = (j < L) ? row[j] : -1e30f;
        m = fmaxf(m, v[k]);
    }
#pragma unroll
    for (int o = 16; o; o >>= 1) m = fmaxf(m, __shfl_xor_sync(0xffffffffu, m, o));
    if ((tid & 31) == 0) red[tid >> 5] = m;
    __syncthreads();
    if (tid == 0) {
        float mm = red[0];
#pragma unroll
        for (int w = 1; w < 8; w++) mm = fmaxf(mm, red[w]);
        bval = mm;
    }
    __syncthreads();
    m = bval;
    __syncthreads();

    float s = 0.0f;
#pragma unroll
    for (int k = 0; k < 8; k++) {
        const int j = tid + k*256;
        v[k] = (j < L) ? __expf(v[k] - m) : 0.0f;
        s += v[k];
    }
#pragma unroll
    for (int o = 16; o; o >>= 1) s += __shfl_xor_sync(0xffffffffu, s, o);
    if ((tid & 31) == 0) red[tid >> 5] = s;
    __syncthreads();
    if (tid == 0) {
        float ss = 0.0f;
#pragma unroll
        for (int w = 0; w < 8; w++) ss += red[w];
        bval = ss;
    }
    __syncthreads();
    const float inv = 1.0f / bval;

    const int end = ((i >> 8) + 1) << 8;
#pragma unroll
    for (int k = 0; k < 8; k++) {
        const int j = tid + k*256;
        if (j < L)        prow[j] = __float2half_rn(v[k] * inv);
        else if (j < end) prow[j] = __ushort_as_half(0);
    }
}

// ---------------------------------------------------------------- launch
extern "C" void kernel_launch(void* const* d_in, const int* in_sizes, int n_in,
                              void* d_out, int out_size)
{
    (void)in_sizes; (void)n_in; (void)out_size;
    const float* x      = (const float*)d_in[0];
    const float* W_kqv  = (const float*)d_in[1];
    const float* b_kqv  = (const float*)d_in[2];
    const float* W_proj = (const float*)d_in[3];
    const float* b_proj = (const float*)d_in[4];
    float* out = (float*)d_out;

    __half *X, *kqv, *P, *O, *Wt, *WtP, *Vt;
    float *S;
    cudaGetSymbolAddress((void**)&X,   g_X);
    cudaGetSymbolAddress((void**)&kqv, g_kqv);
    cudaGetSymbolAddress((void**)&S,   g_S);
    cudaGetSymbolAddress((void**)&P,   g_P);
    cudaGetSymbolAddress((void**)&O,   g_O);
    cudaGetSymbolAddress((void**)&Wt,  g_Wt);
    cudaGetSymbolAddress((void**)&WtP, g_WtP);
    cudaGetSymbolAddress((void**)&Vt,  g_Vt);

    const int B = BATCH, T = SEQ, C = CDIM;
    const float scale = 1.0f / sqrtf((float)T);
    const long sBT3C = (long)T*3*C;

    cudaFuncSetAttribute(gemm_tc<false,false,true,__half>,
        cudaFuncAttributeMaxDynamicSharedMemorySize, SMEM_DYN);
    cudaFuncSetAttribute(gemm_tc<true,false,false,float>,
        cudaFuncAttributeMaxDynamicSharedMemorySize, SMEM_DYN);
    cudaFuncSetAttribute(gemm_tc<false,true,false,__half>,
        cudaFuncAttributeMaxDynamicSharedMemorySize, SMEM_DYN);
    cudaFuncSetAttribute(gemm_tc<false,false,true,float>,
        cudaFuncAttributeMaxDynamicSharedMemorySize, SMEM_DYN);

    // 1) X = fp16(x)
    round_x<<<(B*T*C)/(256*8), 256>>>((const float4*)x, (uint4*)X);

    // 2) Wt = fp16(W_kqv^T)
    transpose_g<float><<<dim3(3*C/32, C/32, 1), dim3(32,8)>>>(W_kqv, Wt, 3*C, C, 0, 0);

    // 3) WtP = fp16(W_proj^T)
    transpose_g<float><<<dim3(C/32, C/32, 1), dim3(32,8)>>>(W_proj, WtP, C, C, 0, 0);

    // 4) kqv = X @ W_kqv + b_kqv   (fp16 out)
    gemm_tc<false,false,true,__half><<<dim3(3*C/BN, (B*T)/BM, 1), 256, SMEM_DYN>>>(
        X, Wt, kqv, b_kqv, C, C, C, 3*C, 0, 0, 0, 1.0f);

    // 5) Vt[b][c][t] = kqv[b*T+t][2C+c]  (fp16 -> fp16)
    transpose_g<__half><<<dim3(C/32, T/32, B), dim3(32,8)>>>(
        kqv + 2*C, Vt, 3*C, T, sBT3C, (long)C*T);

    // 6) S = Q @ K^T * scale (fp32 out, causal block-skip)
    gemm_tc<true,false,false,float><<<dim3(T/BN, T/BM, B), 256, SMEM_DYN>>>(
        kqv + C, kqv, S, nullptr, C, 3*C, 3*C, T,
        sBT3C, sBT3C, (long)T*T, scale);

    // 7) causal softmax: P = fp16(softmax(S)), zeros to 256-block ends
    softmax_causal<<<dim3(T, B, 1), 256>>>(S, P, T);

    // 8) O = P @ V (fp16 out, causal k-limit, heavy rows first)
    gemm_tc<false,true,false,__half><<<dim3(C/BN, T/BM, B), 256, SMEM_DYN>>>(
        P, Vt, O, nullptr, T, T, T, C,
        (long)T*T, (long)C*T, (long)T*C, 1.0f);

    // 9) out = O @ W_proj + b_proj (fp32 out)
    gemm_tc<false,false,true,float><<<dim3(C/BN, (B*T)/BM, 1), 256, SMEM_DYN>>>(
        O, WtP, out, b_proj, C, C, C, C, 0, 0, 0, 1.0f);
}

// round 16
// speedup vs baseline: 2.0796x; 1.1352x over previous
#include <cuda_runtime.h>
#include <cuda_fp16.h>
#include <cstdint>
#include <math.h>

// ---------------------------------------------------------------- constants
#define BATCH 8
#define SEQ   2048
#define CDIM  1024

#define BM 256
#define BN 128
#define NSTAGES 2
#define A_BYTES 32768               // 256 rows x 128B (64 fp16)
#define B_BYTES 16384               // 128 rows x 128B
#define HALF_BYTES (A_BYTES + B_BYTES)      // 48KB: one 64-K sub-tile
#define STAGE_BYTES (2*HALF_BYTES)          // 96KB: one 128-K mega-stage
#define SMEM_DYN (NSTAGES*STAGE_BYTES + 1024)

#define SWZ(x) ((x) ^ (((x)>>3)&0x70))

// ---------------------------------------------------------------- scratch
__device__ __half g_X  [(size_t)BATCH*SEQ*CDIM];    // fp16 x
__device__ __half g_kqv[(size_t)BATCH*SEQ*3*CDIM];  // [B*T, 3C] fp16
__device__ float  g_S  [(size_t)BATCH*SEQ*SEQ];     // [B, T, T] fp32 scores
__device__ __half g_P  [(size_t)BATCH*SEQ*SEQ];     // [B, T, T] fp16 probs
__device__ __half g_O  [(size_t)BATCH*SEQ*CDIM];    // [B*T, C] fp16
__device__ __half g_Wt [(size_t)3*CDIM*CDIM];       // W_kqv^T  [3C, C] fp16
__device__ __half g_WtP[(size_t)CDIM*CDIM];         // W_proj^T [C, C] fp16
__device__ __half g_Vt [(size_t)BATCH*CDIM*SEQ];    // V^T per batch [C, T] fp16

// ---------------------------------------------------------------- ptx utils
__device__ __forceinline__ uint32_t smem_u32(const void* p){
    uint32_t a;
    asm("{ .reg .u64 t; cvta.to.shared.u64 t, %1; cvt.u32.u64 %0, t; }"
        : "=r"(a) : "l"(p));
    return a;
}
__device__ __forceinline__ void cp16(uint32_t dst, const void* src){
    asm volatile("cp.async.cg.shared.global [%0], [%1], 16;" :: "r"(dst), "l"(src));
}
#define MB_INIT(a, c) \
    asm volatile("mbarrier.init.shared.b64 [%0], %1;" :: "r"(a), "r"(c) : "memory")
#define MB_ARRIVE(a) \
    asm volatile("mbarrier.arrive.shared.b64 _, [%0];" :: "r"(a) : "memory")
#define CP_MBAR_NOINC(a) \
    asm volatile("cp.async.mbarrier.arrive.noinc.shared.b64 [%0];" :: "r"(a) : "memory")

#define MB_WAIT_PARITY(a, ph) do { \
    uint32_t _m=(uint32_t)(a), _p=(uint32_t)(ph), _d; \
    asm volatile("{\n\t.reg .pred p;\n\t" \
        "mbarrier.try_wait.parity.acquire.cta.shared::cta.b64 p, [%1], %2;\n\t" \
        "selp.b32 %0, 1, 0, p;\n\t}" : "=r"(_d) : "r"(_m), "r"(_p) : "memory"); \
    if (!_d) { \
        asm volatile("{\n\t.reg .pred P1;\n\tWL_%=:\n\t" \
            "mbarrier.try_wait.parity.acquire.cta.shared::cta.b64 P1, [%0], %1, 0x989680;\n\t" \
            "@P1 bra.uni WD_%=;\n\tbra.uni WL_%=;\n\tWD_%=:\n\t}" \
            :: "r"(_m), "r"(_p) : "memory"); \
    } } while(0)

__device__ __forceinline__ void ldm_x4(uint32_t& r0, uint32_t& r1,
                                       uint32_t& r2, uint32_t& r3, uint32_t a){
    asm volatile("ldmatrix.sync.aligned.m8n8.x4.shared.b16 {%0,%1,%2,%3}, [%4];"
        : "=r"(r0), "=r"(r1), "=r"(r2), "=r"(r3) : "r"(a));
}

__device__ __forceinline__ uint32_t pack_h2(float lo, float hi){
    __half2 h = __floats2half2_rn(lo, hi);
    uint32_t u;
    memcpy(&u, &h, 4);
    return u;
}

// fp16 MMA: D(fp32) = A(fp16) * B(fp16) + C(fp32), m16n8k16
__device__ __forceinline__ void mma_f16(float* c, const uint32_t* a,
                                        uint32_t b0, uint32_t b1){
    asm volatile(
        "mma.sync.aligned.m16n8k16.row.col.f32.f16.f16.f32 "
        "{%0,%1,%2,%3}, {%4,%5,%6,%7}, {%8,%9}, {%0,%1,%2,%3};"
        : "+f"(c[0]), "+f"(c[1]), "+f"(c[2]), "+f"(c[3])
        : "r"(a[0]), "r"(a[1]), "r"(a[2]), "r"(a[3]), "r"(b0), "r"(b1));
}

// ---------------------------------------------------------------- tile loader
// A: 256 rows x 64 fp16 (128B rows, SW128), 8 cp16/thread; B: 128 rows, 4/thread.
__device__ __forceinline__ void load_half_tile(uint32_t sA, uint32_t sB,
    const __half* __restrict__ Ab, const __half* __restrict__ Bb,
    int lda, int ldb, int k0, int tid)
{
#pragma unroll
    for (int i = 0; i < 8; i++) {
        int idx = tid + i*256;
        int row = idx >> 3;
        int ck  = (idx & 7) << 3;              // fp16 elems within row
        uint32_t so = SWZ((uint32_t)(row*128 + ck*2));
        cp16(sA + so, Ab + (size_t)row*lda + k0 + ck);
    }
#pragma unroll
    for (int i = 0; i < 4; i++) {
        int idx = tid + i*256;
        int row = idx >> 3;
        int ck  = (idx & 7) << 3;
        uint32_t so = SWZ((uint32_t)(row*128 + ck*2));
        cp16(sB + so, Bb + (size_t)row*ldb + k0 + ck);
    }
}

// ---------------------------------------------------------------- mma GEMM
// C[bz][m][n] = alpha * sum_k A[bz][m][k]*B[bz][n][k] (+bias[n]). NT, fp16 in,
// fp32 accum, OUTT out. 256x128 CTA tile, 8 warps (4x2) of 64x64.
// mbarrier pipeline, 128-K mega-stages. Fragment double-buffer is persistent
// ACROSS mega-iters: the full-wait + q0-preload of stage it+1 happens inside
// chunk q7 of stage it (covered by q6/q7 MMA drain) -> no serial iter head.
template<bool CSKIP, bool CK, bool HB, typename OUTT>
__global__ void __launch_bounds__(256) gemm_tc(
    const __half* __restrict__ A, const __half* __restrict__ B,
    OUTT* __restrict__ C, const float* __restrict__ bias,
    int K, int lda, int ldb, int ldc, long sA, long sB, long sC, float alpha)
{
    const int bx = blockIdx.x, bz = blockIdx.z;
    const int by = (CSKIP || CK) ? ((int)gridDim.y - 1 - (int)blockIdx.y)
                                 : (int)blockIdx.y;
    if (CSKIP && bx > 2*by + 1) return;

    extern __shared__ char smem[];
    __shared__ uint64_t mbars[2*NSTAGES];   // full0,full1,empty0,empty1
    const uint32_t tb = (smem_u32(smem) + 1023) & ~1023u;
    const uint32_t mb = smem_u32(mbars);
    const int tid = threadIdx.x, wid = tid >> 5, lid = tid & 31;
    const int wm = wid >> 1;       // 4 m-blocks of 64
    const int wn = wid & 1;        // 2 n-blocks of 64

    const __half* Ab = A + (size_t)bz*sA + (size_t)by*BM*lda;
    const __half* Bb = B + (size_t)bz*sB + (size_t)bx*BN*ldb;
    OUTT* Cb = C + (size_t)bz*sC;
    const int kEnd = CK ? min(K, (by + 1)*BM) : K;
    const int iters = kEnd >> 7;   // 128-K mega-iters, >= 2 always

    if (tid == 0) {
#pragma unroll
        for (int s = 0; s < NSTAGES; s++) {
            MB_INIT(mb + 8*s, 256);                 // full[s]
            MB_INIT(mb + 8*(NSTAGES + s), 256);     // empty[s]
        }
    }
    __syncthreads();

    float acc[4][8][4];
#pragma unroll
    for (int i = 0; i < 4; i++)
#pragma unroll
        for (int j = 0; j < 8; j++)
#pragma unroll
            for (int r = 0; r < 4; r++) acc[i][j][r] = 0.0f;

    // ldmatrix lane addressing (bytes in tile): rows (L&15), k-halves (L>>4)
    const uint32_t aRow  = (uint32_t)((wm*64 + (lid & 15)) * 128);
    const uint32_t bRow  = (uint32_t)((wn*64 + (lid & 15)) * 128);
    const uint32_t kSel  = (uint32_t)((lid >> 4) * 16);

    // prologue: produce iter 0 into stage 0
    load_half_tile(tb,              tb + A_BYTES,              Ab, Bb, lda, ldb, 0,  tid);
    load_half_tile(tb + HALF_BYTES, tb + HALF_BYTES + A_BYTES, Ab, Bb, lda, ldb, 64, tid);
    CP_MBAR_NOINC(mb);

    uint32_t afr[2][4][4], bfr[2][4][4];

    // head: wait stage 0, preload its q0 fragments into buffer 0
    MB_WAIT_PARITY(mb, 0);
    {
#pragma unroll
        for (int i = 0; i < 4; i++)
            ldm_x4(afr[0][i][0], afr[0][i][1], afr[0][i][2], afr[0][i][3],
                   tb + SWZ(aRow + (uint32_t)(i*16*128) + kSel));
#pragma unroll
        for (int p = 0; p < 4; p++)
            ldm_x4(bfr[0][p][0], bfr[0][p][1], bfr[0][p][2], bfr[0][p][3],
                   tb + A_BYTES + SWZ(bRow + (uint32_t)(p*16*128) + kSel));
    }

    for (int it = 0; it < iters; ++it) {
        const int cs = it & 1;
        const uint32_t sst = tb + cs*STAGE_BYTES;

        // ---- produce iter it+1 into stage (it+1)&1 (fire-and-forget) ----
        const int nit = it + 1;
        if (nit < iters) {
            const int ps = nit & 1;
            if (nit >= 2)
                MB_WAIT_PARITY(mb + 8*(NSTAGES + ps), ((nit - 2) >> 1) & 1);
            const uint32_t st = tb + ps*STAGE_BYTES;
            load_half_tile(st,              st + A_BYTES,
                           Ab, Bb, lda, ldb, nit*128,      tid);
            load_half_tile(st + HALF_BYTES, st + HALF_BYTES + A_BYTES,
                           Ab, Bb, lda, ldb, nit*128 + 64, tid);
            CP_MBAR_NOINC(mb + 8*ps);
        }

        // ---- 8 chunks; q7 crosses into stage it+1 for its preload ----
#pragma unroll
        for (int q = 0; q < 8; q++) {
            const int cur = q & 1, nxt = cur ^ 1;
            if (q < 7) {
                const uint32_t hb = sst + (uint32_t)(((q+1) >> 2) * HALF_BYTES);
                const uint32_t kb = (uint32_t)(((q+1) & 3) * 32);   // 16 fp16 = 32B
#pragma unroll
                for (int i = 0; i < 4; i++)
                    ldm_x4(afr[nxt][i][0], afr[nxt][i][1],
                           afr[nxt][i][2], afr[nxt][i][3],
                           hb + SWZ(aRow + (uint32_t)(i*16*128) + kb + kSel));
#pragma unroll
                for (int p = 0; p < 4; p++)
                    ldm_x4(bfr[nxt][p][0], bfr[nxt][p][1],
                           bfr[nxt][p][2], bfr[nxt][p][3],
                           hb + A_BYTES + SWZ(bRow + (uint32_t)(p*16*128) + kb + kSel));
            } else if (it + 1 < iters) {
                // stage-crossing preload: wait full[it+1], load its q0 frags.
                // Covered by q6/q7 MMA drain in the tensor pipe.
                MB_WAIT_PARITY(mb + 8*((it+1) & 1), ((it+1) >> 1) & 1);
                const uint32_t nb = tb + ((it+1) & 1)*STAGE_BYTES;
#pragma unroll
                for (int i = 0; i < 4; i++)
                    ldm_x4(afr[nxt][i][0], afr[nxt][i][1],
                           afr[nxt][i][2], afr[nxt][i][3],
                           nb + SWZ(aRow + (uint32_t)(i*16*128) + kSel));
#pragma unroll
                for (int p = 0; p < 4; p++)
                    ldm_x4(bfr[nxt][p][0], bfr[nxt][p][1],
                           bfr[nxt][p][2], bfr[nxt][p][3],
                           nb + A_BYTES + SWZ(bRow + (uint32_t)(p*16*128) + kSel));
            }
            // after q==6's preload (q7 frags), this thread's last smem read
            // of stage cs is done -> release the stage early.
            if (q == 6) MB_ARRIVE(mb + 8*(NSTAGES + cs));

            // bfr[p] = {b0(n=2p), b0(n=2p+1), b1(n=2p), b1(n=2p+1)}
#pragma unroll
            for (int i = 0; i < 4; i++)
#pragma unroll
                for (int j = 0; j < 8; j++)
                    mma_f16(acc[i][j], afr[cur][i],
                            bfr[cur][j >> 1][j & 1],
                            bfr[cur][j >> 1][(j & 1) + 2]);
        }
    }

    const int rowg = by*BM + wm*64 + (lid >> 2);
    const int colg = bx*BN + wn*64 + (lid & 3)*2;
#pragma unroll
    for (int j = 0; j < 8; j++) {
        const int c = colg + j*8;
        float2 bv = make_float2(0.f, 0.f);
        if (HB) bv = *(const float2*)(bias + c);
#pragma unroll
        for (int i = 0; i < 4; i++) {
            const int r = rowg + i*16;
            float2 v0, v1;
            v0.x = acc[i][j][0]*alpha + bv.x;
            v0.y = acc[i][j][1]*alpha + bv.y;
            v1.x = acc[i][j][2]*alpha + bv.x;
            v1.y = acc[i][j][3]*alpha + bv.y;
            if (sizeof(OUTT) == 2) {
                *(uint32_t*)((__half*)(Cb + (size_t)r*ldc) + c)     = pack_h2(v0.x, v0.y);
                *(uint32_t*)((__half*)(Cb + (size_t)(r+8)*ldc) + c) = pack_h2(v1.x, v1.y);
            } else {
                *(float2*)((float*)(Cb + (size_t)r*ldc) + c)     = v0;
                *(float2*)((float*)(Cb + (size_t)(r+8)*ldc) + c) = v1;
            }
        }
    }
}

// ---------------------------------------------------------------- round x
__global__ void __launch_bounds__(256) round_x(
    const float4* __restrict__ in, uint4* __restrict__ out)
{
    const size_t i = (size_t)blockIdx.x * 256 + threadIdx.x;
    float4 a = in[2*i], b = in[2*i + 1];
    uint4 o;
    o.x = pack_h2(a.x, a.y);
    o.y = pack_h2(a.z, a.w);
    o.z = pack_h2(b.x, b.y);
    o.w = pack_h2(b.z, b.w);
    out[i] = o;
}

// ---------------------------------------------------------------- transpose
template<typename TIN>
__global__ void __launch_bounds__(256) transpose_g(
    const TIN* __restrict__ in, __half* __restrict__ out,
    int ldin, int ldout, long sIn, long sOut)
{
    __shared__ __half t[32][34];
    const int b = blockIdx.z;
    in  += (size_t)b * sIn;
    out += (size_t)b * sOut;
    const int x = blockIdx.x * 32;
    const int y = blockIdx.y * 32;
#pragma unroll
    for (int j = threadIdx.y; j < 32; j += 8)
        t[j][threadIdx.x] = __float2half_rn((float)in[(size_t)(y + j)*ldin + x + threadIdx.x]);
    __syncthreads();
#pragma unroll
    for (int j = threadIdx.y; j < 32; j += 8)
        out[(size_t)(x + j)*ldout + y + threadIdx.x] = t[threadIdx.x][j];
}

// ---------------------------------------------------------------- softmax
__global__ __launch_bounds__(256)
void softmax_causal(const float* __restrict__ S, __half* __restrict__ P, int T)
{
    const int i = blockIdx.x;
    const int b = blockIdx.y;
    const float* row = S + ((size_t)b*T + i)*T;
    __half* prow     = P + ((size_t)b*T + i)*T;
    const int L = i + 1;
    const int tid = threadIdx.x;

    __shared__ float red[8];
    __shared__ float bval;

    float v[8];
    float m = -1e30f;
#pragma unroll
    for (int k = 0; k < 8; k++) {
        const int j = tid + k*256;
        v[k] = (j < L) ? row[j] : -1e30f;
        m = fmaxf(m, v[k]);
    }
#pragma unroll
    for (int o = 16; o; o >>= 1) m = fmaxf(m, __shfl_xor_sync(0xffffffffu, m, o));
    if ((tid & 31) == 0) red[tid >> 5] = m;
    __syncthreads();
    if (tid == 0) {
        float mm = red[0];
#pragma unroll
        for (int w = 1; w < 8; w++) mm = fmaxf(mm, red[w]);
        bval = mm;
    }
    __syncthreads();
    m = bval;
    __syncthreads();

    float s = 0.0f;
#pragma unroll
    for (int k = 0; k < 8; k++) {
        const int j = tid + k*256;
        v[k] = (j < L) ? __expf(v[k] - m) : 0.0f;
        s += v[k];
    }
#pragma unroll
    for (int o = 16; o; o >>= 1) s += __shfl_xor_sync(0xffffffffu, s, o);
    if ((tid & 31) == 0) red[tid >> 5] = s;
    __syncthreads();
    if (tid == 0) {
        float ss = 0.0f;
#pragma unroll
        for (int w = 0; w < 8; w++) ss += red[w];
        bval = ss;
    }
    __syncthreads();
    const float inv = 1.0f / bval;

    const int end = ((i >> 8) + 1) << 8;
#pragma unroll
    for (int k = 0; k < 8; k++) {
        const int j = tid + k*256;
        if (j < L)        prow[j] = __float2half_rn(v[k] * inv);
        else if (j < end) prow[j] = __ushort_as_half(0);
    }
}

// ---------------------------------------------------------------- launch
extern "C" void kernel_launch(void* const* d_in, const int* in_sizes, int n_in,
                              void* d_out, int out_size)
{
    (void)in_sizes; (void)n_in; (void)out_size;
    const float* x      = (const float*)d_in[0];
    const float* W_kqv  = (const float*)d_in[1];
    const float* b_kqv  = (const float*)d_in[2];
    const float* W_proj = (const float*)d_in[3];
    const float* b_proj = (const float*)d_in[4];
    float* out = (float*)d_out;

    __half *X, *kqv, *P, *O, *Wt, *WtP, *Vt;
    float *S;
    cudaGetSymbolAddress((void**)&X,   g_X);
    cudaGetSymbolAddress((void**)&kqv, g_kqv);
    cudaGetSymbolAddress((void**)&S,   g_S);
    cudaGetSymbolAddress((void**)&P,   g_P);
    cudaGetSymbolAddress((void**)&O,   g_O);
    cudaGetSymbolAddress((void**)&Wt,  g_Wt);
    cudaGetSymbolAddress((void**)&WtP, g_WtP);
    cudaGetSymbolAddress((void**)&Vt,  g_Vt);

    const int B = BATCH, T = SEQ, C = CDIM;
    const float scale = 1.0f / sqrtf((float)T);
    const long sBT3C = (long)T*3*C;

    cudaFuncSetAttribute(gemm_tc<false,false,true,__half>,
        cudaFuncAttributeMaxDynamicSharedMemorySize, SMEM_DYN);
    cudaFuncSetAttribute(gemm_tc<true,false,false,float>,
        cudaFuncAttributeMaxDynamicSharedMemorySize, SMEM_DYN);
    cudaFuncSetAttribute(gemm_tc<false,true,false,__half>,
        cudaFuncAttributeMaxDynamicSharedMemorySize, SMEM_DYN);
    cudaFuncSetAttribute(gemm_tc<false,false,true,float>,
        cudaFuncAttributeMaxDynamicSharedMemorySize, SMEM_DYN);

    // 1) X = fp16(x)
    round_x<<<(B*T*C)/(256*8), 256>>>((const float4*)x, (uint4*)X);

    // 2) Wt = fp16(W_kqv^T)
    transpose_g<float><<<dim3(3*C/32, C/32, 1), dim3(32,8)>>>(W_kqv, Wt, 3*C, C, 0, 0);

    // 3) WtP = fp16(W_proj^T)
    transpose_g<float><<<dim3(C/32, C/32, 1), dim3(32,8)>>>(W_proj, WtP, C, C, 0, 0);

    // 4) kqv = X @ W_kqv + b_kqv   (fp16 out)
    gemm_tc<false,false,true,__half><<<dim3(3*C/BN, (B*T)/BM, 1), 256, SMEM_DYN>>>(
        X, Wt, kqv, b_kqv, C, C, C, 3*C, 0, 0, 0, 1.0f);

    // 5) Vt[b][c][t] = kqv[b*T+t][2C+c]  (fp16 -> fp16)
    transpose_g<__half><<<dim3(C/32, T/32, B), dim3(32,8)>>>(
        kqv + 2*C, Vt, 3*C, T, sBT3C, (long)C*T);

    // 6) S = Q @ K^T * scale (fp32 out, causal block-skip)
    gemm_tc<true,false,false,float><<<dim3(T/BN, T/BM, B), 256, SMEM_DYN>>>(
        kqv + C, kqv, S, nullptr, C, 3*C, 3*C, T,
        sBT3C, sBT3C, (long)T*T, scale);

    // 7) causal softmax: P = fp16(softmax(S)), zeros to 256-block ends
    softmax_causal<<<dim3(T, B, 1), 256>>>(S, P, T);

    // 8) O = P @ V (fp16 out, causal k-limit, heavy rows first)
    gemm_tc<false,true,false,__half><<<dim3(C/BN, T/BM, B), 256, SMEM_DYN>>>(
        P, Vt, O, nullptr, T, T, T, C,
        (long)T*T, (long)C*T, (long)T*C, 1.0f);

    // 9) out = O @ W_proj + b_proj (fp32 out)
    gemm_tc<false,false,true,float><<<dim3(C/BN, (B*T)/BM, 1), 256, SMEM_DYN>>>(
        O, WtP, out, b_proj, C, C, C, C, 0, 0, 0, 1.0f);
}